// round 5
// baseline (speedup 1.0000x reference)
#include <cuda_runtime.h>
#include <math.h>
#include <stdint.h>

#define BATCH    2048
#define IN_DIM   2048
#define POOLN    32768
#define HIDN     1024
#define MAXP     8192
#define MINP     512

typedef unsigned long long u64;
typedef unsigned int u32;

// ---------------- scratch (device globals: no allocations allowed) ----------
__device__ float g_c1[BATCH * 128];
__device__ float g_h[BATCH * HIDN];
__device__ float g_scores[(size_t)BATCH * POOLN];   // 256 MB
__device__ float g_comp[BATCH];
__device__ int   g_budget;

// ============================================================================
// Double-buffered pipelined GEMM core with register fragment ping-pong.
// Scalar FFMA, strictly ascending-k per output element: numerics bitwise
// frozen vs all previous rounds — only staging/scheduling changed.
// Tiles: C 128x128 per CTA, k-tile 16, 256 threads, 8x8 per thread.
// ============================================================================
#define GEMM_STS(buf)                                                            \
    As[buf][ca0*4+0][r_a]=ra0.x; As[buf][ca0*4+1][r_a]=ra0.y;                    \
    As[buf][ca0*4+2][r_a]=ra0.z; As[buf][ca0*4+3][r_a]=ra0.w;                    \
    As[buf][ca0*4+4][r_a]=ra1.x; As[buf][ca0*4+5][r_a]=ra1.y;                    \
    As[buf][ca0*4+6][r_a]=ra1.z; As[buf][ca0*4+7][r_a]=ra1.w;                    \
    *(float4*)&Bs[buf][r_b][cb0*4]     = rb0;                                    \
    *(float4*)&Bs[buf][r_b][cb0*4 + 4] = rb1;

#define GEMM_LDG(k0)                                                             \
    {   const float* Ap = Abase + (k0);                                          \
        ra0 = *(const float4*)(Ap + ca0*4);                                      \
        ra1 = *(const float4*)(Ap + ca0*4 + 4);                                  \
        const float* Bp = (Bb) + (size_t)((k0) + r_b) * Nstride;                 \
        rb0 = *(const float4*)(Bp + cb0*4);                                      \
        rb1 = *(const float4*)(Bp + cb0*4 + 4);                                  \
    }

#define FRAG_LD(av, bv, buf, k)                                                  \
    {   const float4* a4 = (const float4*)&As[buf][k][tm * 8];                   \
        const float4* b4 = (const float4*)&Bs[buf][k][tn * 8];                   \
        float4 t0 = a4[0], t1 = a4[1];                                           \
        float4 t2 = b4[0], t3 = b4[1];                                           \
        av[0]=t0.x; av[1]=t0.y; av[2]=t0.z; av[3]=t0.w;                          \
        av[4]=t1.x; av[5]=t1.y; av[6]=t1.z; av[7]=t1.w;                          \
        bv[0]=t2.x; bv[1]=t2.y; bv[2]=t2.z; bv[3]=t2.w;                          \
        bv[4]=t3.x; bv[5]=t3.y; bv[6]=t3.z; bv[7]=t3.w;                          \
    }

#define FMA_BLOCK(av, bv)                                                        \
    _Pragma("unroll")                                                            \
    for (int i = 0; i < 8; i++)                                                  \
        _Pragma("unroll")                                                        \
        for (int j = 0; j < 8; j++) acc[i][j] += av[i] * bv[j];

#define GEMM_PIPE(Ab, Bb, KDIM)                                                  \
    float acc[8][8];                                                             \
    _Pragma("unroll")                                                            \
    for (int i = 0; i < 8; i++)                                                  \
        _Pragma("unroll")                                                        \
        for (int j = 0; j < 8; j++) acc[i][j] = 0.0f;                            \
    const int r_a = tid >> 1, ca0 = (tid & 1) * 2;                               \
    const int r_b = tid >> 4, cb0 = (tid & 15) * 2;                              \
    const float* Abase = (Ab) + (size_t)r_a * (KDIM);                            \
    float4 ra0, ra1, rb0, rb1;                                                   \
    GEMM_LDG(0)                                                                  \
    GEMM_STS(0)                                                                  \
    __syncthreads();                                                             \
    float af0[8], af1[8], bf0[8], bf1[8];                                        \
    FRAG_LD(af0, bf0, 0, 0)                                                      \
    const int ITERS = (KDIM) / 16;                                               \
    for (int it = 0; it < ITERS; it++) {                                         \
        const int cur = it & 1;                                                  \
        if (it + 1 < ITERS) { GEMM_LDG((it + 1) * 16) }                          \
        _Pragma("unroll")                                                        \
        for (int k = 0; k < 15; k++) {                                           \
            if (k & 1) { FRAG_LD(af0, bf0, cur, k + 1) FMA_BLOCK(af1, bf1) }     \
            else       { FRAG_LD(af1, bf1, cur, k + 1) FMA_BLOCK(af0, bf0) }     \
        }                                                                        \
        if (it + 1 < ITERS) { GEMM_STS(cur ^ 1) }                                \
        __syncthreads();                                                         \
        if (it + 1 < ITERS) { FRAG_LD(af0, bf0, cur ^ 1, 0) }                    \
        FMA_BLOCK(af1, bf1)                                                      \
    }

// ---------------- Ws2 GEMM: scores = h @ Ws2 + bs2 + noise*0.1 --------------
__global__ void __launch_bounds__(256, 2) sgemm_scores(
    const float* __restrict__ A, const float* __restrict__ B,
    const float* __restrict__ bias, const float* __restrict__ noise,
    float* __restrict__ C)
{
    __shared__ float As[2][16][128];
    __shared__ float Bs[2][16][128];
    const int bx = blockIdx.x, by = blockIdx.y;
    const int tid = threadIdx.x;
    const int tn = tid & 15, tm = tid >> 4;
    const int Nstride = POOLN;
    const float* Ab = A + (size_t)by * 128 * HIDN;
    const float* Bb = B + (size_t)bx * 128;

    GEMM_PIPE(Ab, Bb, HIDN)

    const int col0 = bx * 128 + tn * 8;
    const float4 bi0 = *(const float4*)&bias[col0];
    const float4 bi1 = *(const float4*)&bias[col0 + 4];
#pragma unroll
    for (int i = 0; i < 8; i++) {
        const int row = by * 128 + tm * 8 + i;
        const float* np = noise + (size_t)row * POOLN + col0;
        float4 n0 = *(const float4*)np;
        float4 n1 = *(const float4*)(np + 4);
        float4 o0, o1;
        o0.x = __fadd_rn(__fadd_rn(acc[i][0], bi0.x), __fmul_rn(n0.x, 0.1f));
        o0.y = __fadd_rn(__fadd_rn(acc[i][1], bi0.y), __fmul_rn(n0.y, 0.1f));
        o0.z = __fadd_rn(__fadd_rn(acc[i][2], bi0.z), __fmul_rn(n0.z, 0.1f));
        o0.w = __fadd_rn(__fadd_rn(acc[i][3], bi0.w), __fmul_rn(n0.w, 0.1f));
        o1.x = __fadd_rn(__fadd_rn(acc[i][4], bi1.x), __fmul_rn(n1.x, 0.1f));
        o1.y = __fadd_rn(__fadd_rn(acc[i][5], bi1.y), __fmul_rn(n1.y, 0.1f));
        o1.z = __fadd_rn(__fadd_rn(acc[i][6], bi1.z), __fmul_rn(n1.z, 0.1f));
        o1.w = __fadd_rn(__fadd_rn(acc[i][7], bi1.w), __fmul_rn(n1.w, 0.1f));
        float* cp = C + (size_t)row * POOLN + col0;
        *(float4*)cp = o0;
        *(float4*)(cp + 4) = o1;
    }
}

// ---------------- fused Ws1 + W1c GEMM: relu(x@W + b) -----------------------
// bx in [0,8): h tile (N=1024).  bx == 8: c1 tile (N=128).
__global__ void __launch_bounds__(256, 2) sgemm_fused(
    const float* __restrict__ x,
    const float* __restrict__ Ws1, const float* __restrict__ bs1,
    const float* __restrict__ W1c, const float* __restrict__ b1c)
{
    __shared__ float As[2][16][128];
    __shared__ float Bs[2][16][128];
    const int bx = blockIdx.x, by = blockIdx.y;
    const int tid = threadIdx.x;
    const int tn = tid & 15, tm = tid >> 4;

    const bool is_c1 = (bx == 8);
    const float* Bsel = is_c1 ? W1c : Ws1;
    const float* bias = is_c1 ? b1c : bs1;
    float*       Csel = is_c1 ? g_c1 : g_h;
    const int Nstride = is_c1 ? 128 : HIDN;
    const int cb      = is_c1 ? 0 : bx * 128;

    const float* Ab = x + (size_t)by * 128 * IN_DIM;
    const float* Bb = Bsel + cb;

    GEMM_PIPE(Ab, Bb, IN_DIM)

    const float4 bi0 = *(const float4*)&bias[tn * 8];
    const float4 bi1 = *(const float4*)&bias[tn * 8 + 4];
#pragma unroll
    for (int i = 0; i < 8; i++) {
        const int row = by * 128 + tm * 8 + i;
        float4 o0, o1;
        o0.x = fmaxf(__fadd_rn(acc[i][0], bi0.x), 0.0f);
        o0.y = fmaxf(__fadd_rn(acc[i][1], bi0.y), 0.0f);
        o0.z = fmaxf(__fadd_rn(acc[i][2], bi0.z), 0.0f);
        o0.w = fmaxf(__fadd_rn(acc[i][3], bi0.w), 0.0f);
        o1.x = fmaxf(__fadd_rn(acc[i][4], bi1.x), 0.0f);
        o1.y = fmaxf(__fadd_rn(acc[i][5], bi1.y), 0.0f);
        o1.z = fmaxf(__fadd_rn(acc[i][6], bi1.z), 0.0f);
        o1.w = fmaxf(__fadd_rn(acc[i][7], bi1.w), 0.0f);
        float* cp = Csel + (size_t)row * Nstride + cb + tn * 8;
        *(float4*)cp = o0;
        *(float4*)(cp + 4) = o1;
    }
}

// ---------------- comp stage 2: sigmoid(c1 @ W2c + b2c) ---------------------
__global__ void comp_kernel(const float* __restrict__ W2c,
                            const float* __restrict__ b2c,
                            float* __restrict__ out_comp)
{
    int row  = blockIdx.x * 8 + (threadIdx.x >> 5);
    int lane = threadIdx.x & 31;
    float p = 0.0f;
#pragma unroll
    for (int t = lane; t < 128; t += 32) p += g_c1[row * 128 + t] * W2c[t];
#pragma unroll
    for (int o = 16; o > 0; o >>= 1) p += __shfl_down_sync(0xffffffffu, p, o);
    if (lane == 0) {
        float z = p + b2c[0];
        float c = 1.0f / (1.0f + expf(-z));
        g_comp[row]  = c;
        out_comp[row] = c;
    }
}

// ---------------- budget ----------------------------------------------------
__global__ void budget_kernel(float* __restrict__ out_budget)
{
    __shared__ float ws[32];
    int tid = threadIdx.x;
    float s = g_comp[tid] + g_comp[tid + 1024];
#pragma unroll
    for (int o = 16; o > 0; o >>= 1) s += __shfl_down_sync(0xffffffffu, s, o);
    if ((tid & 31) == 0) ws[tid >> 5] = s;
    __syncthreads();
    if (tid < 32) {
        float v = ws[tid];
#pragma unroll
        for (int o = 16; o > 0; o >>= 1) v += __shfl_down_sync(0xffffffffu, v, o);
        if (tid == 0) {
            float mean  = v / 2048.0f;
            float scale = mean * mean;                 // EXP = 2.0
            float t = 512.0f + 7680.0f * scale;
            int b = (int)floorf(t);
            if (b < MINP) b = MINP;
            if (b > MAXP) b = MAXP;
            g_budget = b;
            out_budget[0] = (float)b;
        }
    }
}

// ============================================================================
// top-k + softmax  (unchanged from R4)
// ============================================================================
__device__ __forceinline__ unsigned f2key(float s) {
    unsigned b = __float_as_uint(s);
    return (b & 0x80000000u) ? ~b : (b | 0x80000000u);   // order-preserving
}
__device__ __forceinline__ float key2f(unsigned k) {
    return __uint_as_float((k & 0x80000000u) ? (k ^ 0x80000000u) : ~k);
}

#define OFF_KEYS   0
#define OFF_SBUFA  131072
#define OFF_HIST   196608
#define OFF_RED    212992
#define TOPK_SMEM  (212992 + 640)

__device__ __forceinline__ u32 scan4096(u32* a, u32* red, int tid,
                                        u32 h[4], u32 ex[4])
{
    const int lane = tid & 31, warp = tid >> 5;
#pragma unroll
    for (int i = 0; i < 4; i++) h[i] = a[tid * 4 + i];
    u32 s = h[0] + h[1] + h[2] + h[3];
    u32 inc = s;
#pragma unroll
    for (int o = 1; o < 32; o <<= 1) {
        u32 n = __shfl_up_sync(0xffffffffu, inc, o);
        if (lane >= o) inc += n;
    }
    if (lane == 31) red[warp] = inc;
    __syncthreads();
    if (tid < 32) {
        u32 v = red[tid];
#pragma unroll
        for (int o = 1; o < 32; o <<= 1) {
            u32 n = __shfl_up_sync(0xffffffffu, v, o);
            if (tid >= o) v += n;
        }
        red[32 + tid] = v;
    }
    __syncthreads();
    u32 wb = (warp == 0) ? 0u : red[32 + warp - 1];
    u32 tb = wb + inc - s;
    ex[0] = tb; ex[1] = ex[0] + h[0]; ex[2] = ex[1] + h[1]; ex[3] = ex[2] + h[2];
#pragma unroll
    for (int i = 0; i < 4; i++) a[tid * 4 + i] = ex[i];
    u32 total = red[32 + 31];
    __syncthreads();
    return total;
}

__device__ __forceinline__ unsigned eqmask4(unsigned d) {
    unsigned m = 0xffffffffu;
#pragma unroll
    for (int b = 0; b < 4; b++) {
        unsigned bal = __ballot_sync(0xffffffffu, (d >> b) & 1u);
        m &= ((d >> b) & 1u) ? bal : ~bal;
    }
    return m;
}

__global__ void __launch_bounds__(1024) topk_kernel(
    float* __restrict__ out_idx, float* __restrict__ out_w)
{
    extern __shared__ unsigned char smem_raw[];
    u32* keys  = (u32*)(smem_raw + OFF_KEYS);
    u64* sbufA = (u64*)(smem_raw + OFF_SBUFA);
    u64* sbufB = (u64*)(smem_raw + OFF_KEYS);     // alias: valid after keys dead
    u32* hist  = (u32*)(smem_raw + OFF_HIST);
    u32* red   = (u32*)(smem_raw + OFF_RED);
    float* fred = (float*)red;

    const int row = blockIdx.x;
    const int tid = threadIdx.x;
    const int warp = tid >> 5, lane = tid & 31;
    const unsigned ltm = (1u << lane) - 1u;
    const float* srow = g_scores + (size_t)row * POOLN;

    for (int j = tid; j < POOLN; j += 1024) keys[j] = f2key(srow[j]);
    __syncthreads();

    // ---- exact k-th largest key via 3-level radix histogram (12/12/8) ----
    unsigned prefix = 0;
    u32 base_gt = 0;
#pragma unroll
    for (int lvl = 0; lvl < 3; lvl++) {
        const int lb   = (lvl < 2) ? 12 : 8;
        const int done = (lvl == 0) ? 0 : (lvl == 1 ? 12 : 24);
#pragma unroll
        for (int i = 0; i < 4; i++) hist[tid * 4 + i] = 0;
        __syncthreads();
        for (int j = tid; j < POOLN; j += 1024) {
            u32 k = keys[j];
            bool part = (done == 0) || ((k >> (32 - done)) == prefix);
            unsigned d = part ? ((k << done) >> (32 - lb)) : 0xFFFFFFFFu;
            unsigned m = __match_any_sync(0xffffffffu, d);
            if (part && (m & ltm) == 0)
                atomicAdd(&hist[d], __popc(m));
        }
        __syncthreads();
        u32 h4[4], ex4[4];
        u32 T = scan4096(hist, red, tid, h4, ex4);
#pragma unroll
        for (int i = 0; i < 4; i++) {
            u32 cg = T - ex4[i] - h4[i];
            if (h4[i] && base_gt + cg < MAXP && base_gt + cg + h4[i] >= MAXP) {
                red[140] = (u32)(tid * 4 + i);
                red[141] = cg;
            }
        }
        __syncthreads();
        prefix = (prefix << lb) | red[140];
        base_gt += red[141];
        __syncthreads();
    }
    const unsigned V = prefix;

    // ---- stable compaction ----
    const int beg = tid * 32;
    int cgt = 0, ceq = 0;
#pragma unroll 8
    for (int j = beg; j < beg + 32; j++) {
        unsigned k = keys[j];
        cgt += (k > V); ceq += (k == V);
    }
    int vg = cgt, ve = ceq;
#pragma unroll
    for (int o = 1; o < 32; o <<= 1) {
        int ng = __shfl_up_sync(0xffffffffu, vg, o);
        int ne = __shfl_up_sync(0xffffffffu, ve, o);
        if (lane >= o) { vg += ng; ve += ne; }
    }
    if (lane == 31) { red[2 + warp] = (u32)vg; red[34 + warp] = (u32)ve; }
    __syncthreads();
    if (tid < 32) {
        int wg = (int)red[2 + tid], we = (int)red[34 + tid];
#pragma unroll
        for (int o = 1; o < 32; o <<= 1) {
            int ng = __shfl_up_sync(0xffffffffu, wg, o);
            int ne = __shfl_up_sync(0xffffffffu, we, o);
            if (tid >= o) { wg += ng; we += ne; }
        }
        red[2 + tid] = (u32)wg; red[34 + tid] = (u32)we;
    }
    __syncthreads();
    int bgt = vg - cgt + (warp ? (int)red[2 + warp - 1] : 0);
    int beq = ve - ceq + (warp ? (int)red[34 + warp - 1] : 0);
    const int count_gt = (int)red[2 + 31];
    const int need_eq  = MAXP - count_gt;

    for (int j = beg; j < beg + 32; j++) {
        unsigned k = keys[j];
        if (k > V) {
            sbufA[bgt++] = ((u64)(~k) << 32) | (unsigned)j;
        } else if (k == V) {
            int r = beq++;
            if (r < need_eq)
                sbufA[count_gt + r] = ((u64)(~V) << 32) | (unsigned)j;
        }
    }
    __syncthreads();

    // ---- stable LSD radix sort: 8 x 4-bit on ~key ----
    u64* src = sbufA;
    u64* dst = sbufB;
#pragma unroll 1
    for (int p = 0; p < 8; p++) {
        const int shift = 32 + 4 * p;
#pragma unroll
        for (int i = 0; i < 4; i++) hist[tid * 4 + i] = 0;
        __syncthreads();
#pragma unroll 1
        for (int e = 0; e < 8; e++) {
            u64 v = src[e * 1024 + tid];
            unsigned d = (unsigned)(v >> shift) & 15u;
            unsigned m = eqmask4(d);
            if ((m & ltm) == 0)
                hist[d * 256 + e * 32 + warp] = (u32)__popc(m);
        }
        __syncthreads();
        u32 h4[4], ex4[4];
        scan4096(hist, red, tid, h4, ex4);
#pragma unroll 1
        for (int e = 0; e < 8; e++) {
            u64 v = src[e * 1024 + tid];
            unsigned d = (unsigned)(v >> shift) & 15u;
            unsigned m = eqmask4(d);
            unsigned rk = (unsigned)__popc(m & ltm);
            dst[hist[d * 256 + e * 32 + warp] + rk] = v;
        }
        __syncthreads();
        u64* t = src; src = dst; dst = t;
    }

    // ---- softmax over first `budget` entries ----
    const float s0 = key2f(~(unsigned)(src[0] >> 32));
    const int budget = g_budget;
    float part = 0.0f;
    float ev[8]; int iv[8];
#pragma unroll
    for (int i = 0; i < 8; i++) {
        int pp = tid + i * 1024;
        u64 v = src[pp];
        unsigned key = ~(unsigned)(v >> 32);
        iv[i] = (int)(v & 0xFFFFFFFFu);
        float e = (pp < budget) ? expf(key2f(key) - s0) : 0.0f;
        ev[i] = e;
        part += e;
    }
#pragma unroll
    for (int o = 16; o > 0; o >>= 1) part += __shfl_down_sync(0xffffffffu, part, o);
    __syncthreads();
    if (lane == 0) fred[64 + warp] = part;
    __syncthreads();
    if (tid == 0) {
        float s = 0.0f;
        for (int w = 0; w < 32; w++) s += fred[64 + w];
        fred[96] = s;
    }
    __syncthreads();
    const float denom = fred[96];

#pragma unroll
    for (int i = 0; i < 8; i++) {
        int pp = tid + i * 1024;
        out_idx[(size_t)row * MAXP + pp] = (float)iv[i];
        out_w  [(size_t)row * MAXP + pp] = ev[i] / denom;
    }
}

// ---------------- launch -----------------------------------------------------
extern "C" void kernel_launch(void* const* d_in, const int* in_sizes, int n_in,
                              void* d_out, int out_size)
{
    const float* x    = (const float*)d_in[0];
    const float* noise= (const float*)d_in[1];
    const float* W1c  = (const float*)d_in[2];
    const float* b1c  = (const float*)d_in[3];
    const float* W2c  = (const float*)d_in[4];
    const float* b2c  = (const float*)d_in[5];
    const float* Ws1  = (const float*)d_in[6];
    const float* bs1  = (const float*)d_in[7];
    const float* Ws2  = (const float*)d_in[8];
    const float* bs2  = (const float*)d_in[9];

    float* out        = (float*)d_out;
    float* out_idx    = out;
    float* out_budget = out + (size_t)BATCH * MAXP;
    float* out_w      = out_budget + 1;
    float* out_comp   = out_w + (size_t)BATCH * MAXP;

    float *hp, *sp;
    cudaGetSymbolAddress((void**)&hp, g_h);
    cudaGetSymbolAddress((void**)&sp, g_scores);

    // fused: h = relu(x@Ws1+bs1)  and  c1 = relu(x@W1c+b1c)  in one wave
    sgemm_fused<<<dim3(9, 16), 256>>>(x, Ws1, bs1, W1c, b1c);
    comp_kernel<<<256, 256>>>(W2c, b2c, out_comp);
    budget_kernel<<<1, 1024>>>(out_budget);

    // scores = h@Ws2 + bs2 + noise*0.1
    sgemm_scores<<<dim3(256, 16), 256>>>(hp, Ws2, bs2, noise, sp);

    // top-k + softmax
    cudaFuncSetAttribute(topk_kernel, cudaFuncAttributeMaxDynamicSharedMemorySize, TOPK_SMEM);
    topk_kernel<<<BATCH, 1024, TOPK_SMEM>>>(out_idx, out_w);
}

// round 6
// speedup vs baseline: 1.0418x; 1.0418x over previous
#include <cuda_runtime.h>
#include <math.h>
#include <stdint.h>

#define BATCH    2048
#define IN_DIM   2048
#define POOLN    32768
#define HIDN     1024
#define MAXP     8192
#define MINP     512

typedef unsigned long long u64;
typedef unsigned int u32;

// ---------------- scratch (device globals: no allocations allowed) ----------
__device__ float g_c1[BATCH * 128];
__device__ float g_hT[(size_t)HIDN * BATCH];        // h transposed: [k][row]
__device__ float g_scores[(size_t)BATCH * POOLN];   // 256 MB
__device__ float g_comp[BATCH];
__device__ int   g_budget;

// ---------------- cp.async helpers ------------------------------------------
__device__ __forceinline__ void cpa16(void* smem, const void* gmem) {
    unsigned s = (unsigned)__cvta_generic_to_shared(smem);
    asm volatile("cp.async.cg.shared.global [%0], [%1], 16;" :: "r"(s), "l"(gmem));
}
#define CP_COMMIT()  asm volatile("cp.async.commit_group;")
#define CP_WAIT(n)   asm volatile("cp.async.wait_group %0;" :: "n"(n))

// ============================================================================
// R4 GEMM core (LDG+STS transpose staging, double-buffered). Scalar FFMA,
// strictly ascending-k per output element: numerics bitwise-frozen.
// Used by the fused x-GEMM (K=2048).
// ============================================================================
#define GEMM_STS(buf)                                                            \
    As[buf][ca0*4+0][r_a]=ra0.x; As[buf][ca0*4+1][r_a]=ra0.y;                    \
    As[buf][ca0*4+2][r_a]=ra0.z; As[buf][ca0*4+3][r_a]=ra0.w;                    \
    As[buf][ca0*4+4][r_a]=ra1.x; As[buf][ca0*4+5][r_a]=ra1.y;                    \
    As[buf][ca0*4+6][r_a]=ra1.z; As[buf][ca0*4+7][r_a]=ra1.w;                    \
    *(float4*)&Bs[buf][r_b][cb0*4]     = rb0;                                    \
    *(float4*)&Bs[buf][r_b][cb0*4 + 4] = rb1;

#define GEMM_LDG(k0)                                                             \
    {   const float* Ap = Abase + (k0);                                          \
        ra0 = *(const float4*)(Ap + ca0*4);                                      \
        ra1 = *(const float4*)(Ap + ca0*4 + 4);                                  \
        const float* Bp = (Bb) + (size_t)((k0) + r_b) * Nstride;                 \
        rb0 = *(const float4*)(Bp + cb0*4);                                      \
        rb1 = *(const float4*)(Bp + cb0*4 + 4);                                  \
    }

#define GEMM_PIPE(Ab, Bb, KDIM)                                                  \
    float acc[8][8];                                                             \
    _Pragma("unroll")                                                            \
    for (int i = 0; i < 8; i++)                                                  \
        _Pragma("unroll")                                                        \
        for (int j = 0; j < 8; j++) acc[i][j] = 0.0f;                            \
    const int r_a = tid >> 1, ca0 = (tid & 1) * 2;                               \
    const int r_b = tid >> 4, cb0 = (tid & 15) * 2;                              \
    const float* Abase = (Ab) + (size_t)r_a * (KDIM);                            \
    float4 ra0, ra1, rb0, rb1;                                                   \
    GEMM_LDG(0)                                                                  \
    GEMM_STS(0)                                                                  \
    __syncthreads();                                                             \
    const int ITERS = (KDIM) / 16;                                               \
    for (int it = 0; it < ITERS; it++) {                                         \
        const int cur = it & 1;                                                  \
        if (it + 1 < ITERS) { GEMM_LDG((it + 1) * 16) }                          \
        _Pragma("unroll")                                                        \
        for (int k = 0; k < 16; k++) {                                           \
            float a[8], b[8];                                                    \
            const float4* a4 = (const float4*)&As[cur][k][tm * 8];               \
            const float4* b4 = (const float4*)&Bs[cur][k][tn * 8];               \
            float4 av0 = a4[0], av1 = a4[1];                                     \
            float4 bv0 = b4[0], bv1 = b4[1];                                     \
            a[0]=av0.x; a[1]=av0.y; a[2]=av0.z; a[3]=av0.w;                      \
            a[4]=av1.x; a[5]=av1.y; a[6]=av1.z; a[7]=av1.w;                      \
            b[0]=bv0.x; b[1]=bv0.y; b[2]=bv0.z; b[3]=bv0.w;                      \
            b[4]=bv1.x; b[5]=bv1.y; b[6]=bv1.z; b[7]=bv1.w;                      \
            _Pragma("unroll")                                                    \
            for (int i = 0; i < 8; i++)                                          \
                _Pragma("unroll")                                                \
                for (int j = 0; j < 8; j++) acc[i][j] += a[i] * b[j];            \
        }                                                                        \
        if (it + 1 < ITERS) { GEMM_STS(cur ^ 1) }                                \
        __syncthreads();                                                         \
    }

// ---------------- fused Ws1 + W1c GEMM --------------------------------------
// bx in [0,8): h tile -> stored TRANSPOSED into g_hT.  bx == 8: c1 tile.
__global__ void __launch_bounds__(256, 2) sgemm_fused(
    const float* __restrict__ x,
    const float* __restrict__ Ws1, const float* __restrict__ bs1,
    const float* __restrict__ W1c, const float* __restrict__ b1c)
{
    __shared__ float As[2][16][128];
    __shared__ float Bs[2][16][128];
    const int bx = blockIdx.x, by = blockIdx.y;
    const int tid = threadIdx.x;
    const int tn = tid & 15, tm = tid >> 4;

    const bool is_c1 = (bx == 8);
    const float* Bsel = is_c1 ? W1c : Ws1;
    const float* bias = is_c1 ? b1c : bs1;
    const int Nstride = is_c1 ? 128 : HIDN;
    const int cb      = is_c1 ? 0 : bx * 128;

    const float* Ab = x + (size_t)by * 128 * IN_DIM;
    const float* Bb = Bsel + cb;

    GEMM_PIPE(Ab, Bb, IN_DIM)

    const float4 bi0 = *(const float4*)&bias[tn * 8];
    const float4 bi1 = *(const float4*)&bias[tn * 8 + 4];
    float r_[8][8];
#pragma unroll
    for (int i = 0; i < 8; i++) {
        r_[i][0] = fmaxf(__fadd_rn(acc[i][0], bi0.x), 0.0f);
        r_[i][1] = fmaxf(__fadd_rn(acc[i][1], bi0.y), 0.0f);
        r_[i][2] = fmaxf(__fadd_rn(acc[i][2], bi0.z), 0.0f);
        r_[i][3] = fmaxf(__fadd_rn(acc[i][3], bi0.w), 0.0f);
        r_[i][4] = fmaxf(__fadd_rn(acc[i][4], bi1.x), 0.0f);
        r_[i][5] = fmaxf(__fadd_rn(acc[i][5], bi1.y), 0.0f);
        r_[i][6] = fmaxf(__fadd_rn(acc[i][6], bi1.z), 0.0f);
        r_[i][7] = fmaxf(__fadd_rn(acc[i][7], bi1.w), 0.0f);
    }
    const int row0 = by * 128 + tm * 8;
    if (!is_c1) {
        // transposed store: g_hT[col][row]
#pragma unroll
        for (int j = 0; j < 8; j++) {
            const int col = cb + tn * 8 + j;
            float4 lo = make_float4(r_[0][j], r_[1][j], r_[2][j], r_[3][j]);
            float4 hi = make_float4(r_[4][j], r_[5][j], r_[6][j], r_[7][j]);
            float* cp = g_hT + (size_t)col * BATCH + row0;
            *(float4*)cp = lo;
            *(float4*)(cp + 4) = hi;
        }
    } else {
#pragma unroll
        for (int i = 0; i < 8; i++) {
            float* cp = g_c1 + (size_t)(row0 + i) * 128 + tn * 8;
            *(float4*)cp = make_float4(r_[i][0], r_[i][1], r_[i][2], r_[i][3]);
            *(float4*)(cp + 4) = make_float4(r_[i][4], r_[i][5], r_[i][6], r_[i][7]);
        }
    }
}

// ============================================================================
// scores GEMM: cp.async 2-stage + register fragment ping-pong, 1 CTA/SM.
// A = hT [HIDN][BATCH] (k-major), B = Ws2 [HIDN][POOLN] (k-major).
// acc[i][j] accumulates ascending k -> scores bitwise identical.
// ============================================================================
#define FRAG_LD(av, bv, buf, k)                                                  \
    {   const float4* a4 = (const float4*)&As[buf][k][tm * 8];                   \
        const float4* b4 = (const float4*)&Bs[buf][k][tn * 8];                   \
        float4 t0 = a4[0], t1 = a4[1];                                           \
        float4 t2 = b4[0], t3 = b4[1];                                           \
        av[0]=t0.x; av[1]=t0.y; av[2]=t0.z; av[3]=t0.w;                          \
        av[4]=t1.x; av[5]=t1.y; av[6]=t1.z; av[7]=t1.w;                          \
        bv[0]=t2.x; bv[1]=t2.y; bv[2]=t2.z; bv[3]=t2.w;                          \
        bv[4]=t3.x; bv[5]=t3.y; bv[6]=t3.z; bv[7]=t3.w;                          \
    }

#define FMA_BLOCK(av, bv)                                                        \
    _Pragma("unroll")                                                            \
    for (int i = 0; i < 8; i++)                                                  \
        _Pragma("unroll")                                                        \
        for (int j = 0; j < 8; j++) acc[i][j] += av[i] * bv[j];

__global__ void __launch_bounds__(256, 1) sgemm_scores_ca(
    const float* __restrict__ AT, const float* __restrict__ B,
    const float* __restrict__ bias, const float* __restrict__ noise,
    float* __restrict__ C)
{
    __shared__ float As[2][16][128];
    __shared__ float Bs[2][16][128];
    const int bx = blockIdx.x, by = blockIdx.y;
    const int tid = threadIdx.x;
    const int tn = tid & 15, tm = tid >> 4;

    // copy mapping: each thread copies 32B at (row r_c, float col cc) of each tile
    const int r_c = tid >> 4;          // 0..15
    const int cc  = (tid & 15) * 8;    // 0..120

    const float* gA = AT + (size_t)r_c * BATCH + by * 128 + cc;
    const float* gB = B  + (size_t)r_c * POOLN + bx * 128 + cc;
    const size_t stepA = (size_t)16 * BATCH;
    const size_t stepB = (size_t)16 * POOLN;

#define CPA_TILE(buf)                                                            \
    {   float* dA = &As[buf][r_c][cc];                                           \
        cpa16(dA, gA); cpa16(dA + 4, gA + 4);                                    \
        float* dB = &Bs[buf][r_c][cc];                                           \
        cpa16(dB, gB); cpa16(dB + 4, gB + 4);                                    \
        CP_COMMIT();                                                             \
        gA += stepA; gB += stepB; }

    float acc[8][8];
#pragma unroll
    for (int i = 0; i < 8; i++)
#pragma unroll
        for (int j = 0; j < 8; j++) acc[i][j] = 0.0f;

    CPA_TILE(0)
    CPA_TILE(1)
    CP_WAIT(1);
    __syncthreads();

    float af0[8], af1[8], bf0[8], bf1[8];
    FRAG_LD(af0, bf0, 0, 0)

    const int ITERS = HIDN / 16;   // 64
    for (int it = 0; it < ITERS; it++) {
        const int cur = it & 1;
#pragma unroll
        for (int k = 0; k < 15; k++) {
            if (k & 1) { FRAG_LD(af0, bf0, cur, k + 1) FMA_BLOCK(af1, bf1) }
            else       { FRAG_LD(af1, bf1, cur, k + 1) FMA_BLOCK(af0, bf0) }
        }
        __syncthreads();                       // all reads of buf `cur` done
        if (it + 2 < ITERS) { CPA_TILE(cur) }  // refill buf `cur` for it+2
        if (it + 1 < ITERS) {
            if (it + 2 < ITERS) { CP_WAIT(1); } else { CP_WAIT(0); }
            __syncthreads();                   // buf cur^1 landed
            FRAG_LD(af0, bf0, cur ^ 1, 0)      // prefetch next tile k=0
        }
        FMA_BLOCK(af1, bf1)                    // k = 15
    }

    const int col0 = bx * 128 + tn * 8;
    const float4 bi0 = *(const float4*)&bias[col0];
    const float4 bi1 = *(const float4*)&bias[col0 + 4];
#pragma unroll
    for (int i = 0; i < 8; i++) {
        const int row = by * 128 + tm * 8 + i;
        const float* np = noise + (size_t)row * POOLN + col0;
        float4 n0 = *(const float4*)np;
        float4 n1 = *(const float4*)(np + 4);
        float4 o0, o1;
        o0.x = __fadd_rn(__fadd_rn(acc[i][0], bi0.x), __fmul_rn(n0.x, 0.1f));
        o0.y = __fadd_rn(__fadd_rn(acc[i][1], bi0.y), __fmul_rn(n0.y, 0.1f));
        o0.z = __fadd_rn(__fadd_rn(acc[i][2], bi0.z), __fmul_rn(n0.z, 0.1f));
        o0.w = __fadd_rn(__fadd_rn(acc[i][3], bi0.w), __fmul_rn(n0.w, 0.1f));
        o1.x = __fadd_rn(__fadd_rn(acc[i][4], bi1.x), __fmul_rn(n1.x, 0.1f));
        o1.y = __fadd_rn(__fadd_rn(acc[i][5], bi1.y), __fmul_rn(n1.y, 0.1f));
        o1.z = __fadd_rn(__fadd_rn(acc[i][6], bi1.z), __fmul_rn(n1.z, 0.1f));
        o1.w = __fadd_rn(__fadd_rn(acc[i][7], bi1.w), __fmul_rn(n1.w, 0.1f));
        float* cp = C + (size_t)row * POOLN + col0;
        *(float4*)cp = o0;
        *(float4*)(cp + 4) = o1;
    }
}

// ---------------- comp stage 2: sigmoid(c1 @ W2c + b2c) ---------------------
__global__ void comp_kernel(const float* __restrict__ W2c,
                            const float* __restrict__ b2c,
                            float* __restrict__ out_comp)
{
    int row  = blockIdx.x * 8 + (threadIdx.x >> 5);
    int lane = threadIdx.x & 31;
    float p = 0.0f;
#pragma unroll
    for (int t = lane; t < 128; t += 32) p += g_c1[row * 128 + t] * W2c[t];
#pragma unroll
    for (int o = 16; o > 0; o >>= 1) p += __shfl_down_sync(0xffffffffu, p, o);
    if (lane == 0) {
        float z = p + b2c[0];
        float c = 1.0f / (1.0f + expf(-z));
        g_comp[row]  = c;
        out_comp[row] = c;
    }
}

// ---------------- budget ----------------------------------------------------
__global__ void budget_kernel(float* __restrict__ out_budget)
{
    __shared__ float ws[32];
    int tid = threadIdx.x;
    float s = g_comp[tid] + g_comp[tid + 1024];
#pragma unroll
    for (int o = 16; o > 0; o >>= 1) s += __shfl_down_sync(0xffffffffu, s, o);
    if ((tid & 31) == 0) ws[tid >> 5] = s;
    __syncthreads();
    if (tid < 32) {
        float v = ws[tid];
#pragma unroll
        for (int o = 16; o > 0; o >>= 1) v += __shfl_down_sync(0xffffffffu, v, o);
        if (tid == 0) {
            float mean  = v / 2048.0f;
            float scale = mean * mean;                 // EXP = 2.0
            float t = 512.0f + 7680.0f * scale;
            int b = (int)floorf(t);
            if (b < MINP) b = MINP;
            if (b > MAXP) b = MAXP;
            g_budget = b;
            out_budget[0] = (float)b;
        }
    }
}

// ============================================================================
// top-k + softmax  (unchanged from R4)
// ============================================================================
__device__ __forceinline__ unsigned f2key(float s) {
    unsigned b = __float_as_uint(s);
    return (b & 0x80000000u) ? ~b : (b | 0x80000000u);   // order-preserving
}
__device__ __forceinline__ float key2f(unsigned k) {
    return __uint_as_float((k & 0x80000000u) ? (k ^ 0x80000000u) : ~k);
}

#define OFF_KEYS   0
#define OFF_SBUFA  131072
#define OFF_HIST   196608
#define OFF_RED    212992
#define TOPK_SMEM  (212992 + 640)

__device__ __forceinline__ u32 scan4096(u32* a, u32* red, int tid,
                                        u32 h[4], u32 ex[4])
{
    const int lane = tid & 31, warp = tid >> 5;
#pragma unroll
    for (int i = 0; i < 4; i++) h[i] = a[tid * 4 + i];
    u32 s = h[0] + h[1] + h[2] + h[3];
    u32 inc = s;
#pragma unroll
    for (int o = 1; o < 32; o <<= 1) {
        u32 n = __shfl_up_sync(0xffffffffu, inc, o);
        if (lane >= o) inc += n;
    }
    if (lane == 31) red[warp] = inc;
    __syncthreads();
    if (tid < 32) {
        u32 v = red[tid];
#pragma unroll
        for (int o = 1; o < 32; o <<= 1) {
            u32 n = __shfl_up_sync(0xffffffffu, v, o);
            if (tid >= o) v += n;
        }
        red[32 + tid] = v;
    }
    __syncthreads();
    u32 wb = (warp == 0) ? 0u : red[32 + warp - 1];
    u32 tb = wb + inc - s;
    ex[0] = tb; ex[1] = ex[0] + h[0]; ex[2] = ex[1] + h[1]; ex[3] = ex[2] + h[2];
#pragma unroll
    for (int i = 0; i < 4; i++) a[tid * 4 + i] = ex[i];
    u32 total = red[32 + 31];
    __syncthreads();
    return total;
}

__device__ __forceinline__ unsigned eqmask4(unsigned d) {
    unsigned m = 0xffffffffu;
#pragma unroll
    for (int b = 0; b < 4; b++) {
        unsigned bal = __ballot_sync(0xffffffffu, (d >> b) & 1u);
        m &= ((d >> b) & 1u) ? bal : ~bal;
    }
    return m;
}

__global__ void __launch_bounds__(1024) topk_kernel(
    float* __restrict__ out_idx, float* __restrict__ out_w)
{
    extern __shared__ unsigned char smem_raw[];
    u32* keys  = (u32*)(smem_raw + OFF_KEYS);
    u64* sbufA = (u64*)(smem_raw + OFF_SBUFA);
    u64* sbufB = (u64*)(smem_raw + OFF_KEYS);     // alias: valid after keys dead
    u32* hist  = (u32*)(smem_raw + OFF_HIST);
    u32* red   = (u32*)(smem_raw + OFF_RED);
    float* fred = (float*)red;

    const int row = blockIdx.x;
    const int tid = threadIdx.x;
    const int warp = tid >> 5, lane = tid & 31;
    const unsigned ltm = (1u << lane) - 1u;
    const float* srow = g_scores + (size_t)row * POOLN;

    for (int j = tid; j < POOLN; j += 1024) keys[j] = f2key(srow[j]);
    __syncthreads();

    // ---- exact k-th largest key via 3-level radix histogram (12/12/8) ----
    unsigned prefix = 0;
    u32 base_gt = 0;
#pragma unroll
    for (int lvl = 0; lvl < 3; lvl++) {
        const int lb   = (lvl < 2) ? 12 : 8;
        const int done = (lvl == 0) ? 0 : (lvl == 1 ? 12 : 24);
#pragma unroll
        for (int i = 0; i < 4; i++) hist[tid * 4 + i] = 0;
        __syncthreads();
        for (int j = tid; j < POOLN; j += 1024) {
            u32 k = keys[j];
            bool part = (done == 0) || ((k >> (32 - done)) == prefix);
            unsigned d = part ? ((k << done) >> (32 - lb)) : 0xFFFFFFFFu;
            unsigned m = __match_any_sync(0xffffffffu, d);
            if (part && (m & ltm) == 0)
                atomicAdd(&hist[d], __popc(m));
        }
        __syncthreads();
        u32 h4[4], ex4[4];
        u32 T = scan4096(hist, red, tid, h4, ex4);
#pragma unroll
        for (int i = 0; i < 4; i++) {
            u32 cg = T - ex4[i] - h4[i];
            if (h4[i] && base_gt + cg < MAXP && base_gt + cg + h4[i] >= MAXP) {
                red[140] = (u32)(tid * 4 + i);
                red[141] = cg;
            }
        }
        __syncthreads();
        prefix = (prefix << lb) | red[140];
        base_gt += red[141];
        __syncthreads();
    }
    const unsigned V = prefix;

    // ---- stable compaction ----
    const int beg = tid * 32;
    int cgt = 0, ceq = 0;
#pragma unroll 8
    for (int j = beg; j < beg + 32; j++) {
        unsigned k = keys[j];
        cgt += (k > V); ceq += (k == V);
    }
    int vg = cgt, ve = ceq;
#pragma unroll
    for (int o = 1; o < 32; o <<= 1) {
        int ng = __shfl_up_sync(0xffffffffu, vg, o);
        int ne = __shfl_up_sync(0xffffffffu, ve, o);
        if (lane >= o) { vg += ng; ve += ne; }
    }
    if (lane == 31) { red[2 + warp] = (u32)vg; red[34 + warp] = (u32)ve; }
    __syncthreads();
    if (tid < 32) {
        int wg = (int)red[2 + tid], we = (int)red[34 + tid];
#pragma unroll
        for (int o = 1; o < 32; o <<= 1) {
            int ng = __shfl_up_sync(0xffffffffu, wg, o);
            int ne = __shfl_up_sync(0xffffffffu, we, o);
            if (tid >= o) { wg += ng; we += ne; }
        }
        red[2 + tid] = (u32)wg; red[34 + tid] = (u32)we;
    }
    __syncthreads();
    int bgt = vg - cgt + (warp ? (int)red[2 + warp - 1] : 0);
    int beq = ve - ceq + (warp ? (int)red[34 + warp - 1] : 0);
    const int count_gt = (int)red[2 + 31];
    const int need_eq  = MAXP - count_gt;

    for (int j = beg; j < beg + 32; j++) {
        unsigned k = keys[j];
        if (k > V) {
            sbufA[bgt++] = ((u64)(~k) << 32) | (unsigned)j;
        } else if (k == V) {
            int r = beq++;
            if (r < need_eq)
                sbufA[count_gt + r] = ((u64)(~V) << 32) | (unsigned)j;
        }
    }
    __syncthreads();

    // ---- stable LSD radix sort: 8 x 4-bit on ~key ----
    u64* src = sbufA;
    u64* dst = sbufB;
#pragma unroll 1
    for (int p = 0; p < 8; p++) {
        const int shift = 32 + 4 * p;
#pragma unroll
        for (int i = 0; i < 4; i++) hist[tid * 4 + i] = 0;
        __syncthreads();
#pragma unroll 1
        for (int e = 0; e < 8; e++) {
            u64 v = src[e * 1024 + tid];
            unsigned d = (unsigned)(v >> shift) & 15u;
            unsigned m = eqmask4(d);
            if ((m & ltm) == 0)
                hist[d * 256 + e * 32 + warp] = (u32)__popc(m);
        }
        __syncthreads();
        u32 h4[4], ex4[4];
        scan4096(hist, red, tid, h4, ex4);
#pragma unroll 1
        for (int e = 0; e < 8; e++) {
            u64 v = src[e * 1024 + tid];
            unsigned d = (unsigned)(v >> shift) & 15u;
            unsigned m = eqmask4(d);
            unsigned rk = (unsigned)__popc(m & ltm);
            dst[hist[d * 256 + e * 32 + warp] + rk] = v;
        }
        __syncthreads();
        u64* t = src; src = dst; dst = t;
    }

    // ---- softmax over first `budget` entries ----
    const float s0 = key2f(~(unsigned)(src[0] >> 32));
    const int budget = g_budget;
    float part = 0.0f;
    float ev[8]; int iv[8];
#pragma unroll
    for (int i = 0; i < 8; i++) {
        int pp = tid + i * 1024;
        u64 v = src[pp];
        unsigned key = ~(unsigned)(v >> 32);
        iv[i] = (int)(v & 0xFFFFFFFFu);
        float e = (pp < budget) ? expf(key2f(key) - s0) : 0.0f;
        ev[i] = e;
        part += e;
    }
#pragma unroll
    for (int o = 16; o > 0; o >>= 1) part += __shfl_down_sync(0xffffffffu, part, o);
    __syncthreads();
    if (lane == 0) fred[64 + warp] = part;
    __syncthreads();
    if (tid == 0) {
        float s = 0.0f;
        for (int w = 0; w < 32; w++) s += fred[64 + w];
        fred[96] = s;
    }
    __syncthreads();
    const float denom = fred[96];

#pragma unroll
    for (int i = 0; i < 8; i++) {
        int pp = tid + i * 1024;
        out_idx[(size_t)row * MAXP + pp] = (float)iv[i];
        out_w  [(size_t)row * MAXP + pp] = ev[i] / denom;
    }
}

// ---------------- launch -----------------------------------------------------
extern "C" void kernel_launch(void* const* d_in, const int* in_sizes, int n_in,
                              void* d_out, int out_size)
{
    const float* x    = (const float*)d_in[0];
    const float* noise= (const float*)d_in[1];
    const float* W1c  = (const float*)d_in[2];
    const float* b1c  = (const float*)d_in[3];
    const float* W2c  = (const float*)d_in[4];
    const float* b2c  = (const float*)d_in[5];
    const float* Ws1  = (const float*)d_in[6];
    const float* bs1  = (const float*)d_in[7];
    const float* Ws2  = (const float*)d_in[8];
    const float* bs2  = (const float*)d_in[9];

    float* out        = (float*)d_out;
    float* out_idx    = out;
    float* out_budget = out + (size_t)BATCH * MAXP;
    float* out_w      = out_budget + 1;
    float* out_comp   = out_w + (size_t)BATCH * MAXP;

    float *hTp, *sp;
    cudaGetSymbolAddress((void**)&hTp, g_hT);
    cudaGetSymbolAddress((void**)&sp,  g_scores);

    // fused: hT = relu(x@Ws1+bs1)^T  and  c1 = relu(x@W1c+b1c)  in one wave
    sgemm_fused<<<dim3(9, 16), 256>>>(x, Ws1, bs1, W1c, b1c);
    comp_kernel<<<256, 256>>>(W2c, b2c, out_comp);
    budget_kernel<<<1, 1024>>>(out_budget);

    // scores = h@Ws2 + bs2 + noise*0.1   (A = hT, both operands k-major)
    sgemm_scores_ca<<<dim3(256, 16), 256>>>(hTp, Ws2, bs2, noise, sp);

    // top-k + softmax
    cudaFuncSetAttribute(topk_kernel, cudaFuncAttributeMaxDynamicSharedMemorySize, TOPK_SMEM);
    topk_kernel<<<BATCH, 1024, TOPK_SMEM>>>(out_idx, out_w);
}

// round 7
// speedup vs baseline: 1.1058x; 1.0614x over previous
#include <cuda_runtime.h>
#include <math.h>
#include <stdint.h>

#define BATCH    2048
#define IN_DIM   2048
#define POOLN    32768
#define HIDN     1024
#define MAXP     8192
#define MINP     512

typedef unsigned long long u64;
typedef unsigned int u32;

// ---------------- scratch (device globals: no allocations allowed) ----------
__device__ float g_c1[BATCH * 128];
__device__ float g_hT[(size_t)HIDN * BATCH];        // h transposed: [k][row]
__device__ float g_scores[(size_t)BATCH * POOLN];   // 256 MB
__device__ float g_comp[BATCH];
__device__ int   g_budget;

// ---------------- cp.async helpers ------------------------------------------
__device__ __forceinline__ void cpa16(void* smem, const void* gmem) {
    unsigned s = (unsigned)__cvta_generic_to_shared(smem);
    asm volatile("cp.async.cg.shared.global [%0], [%1], 16;" :: "r"(s), "l"(gmem));
}
#define CP_COMMIT()  asm volatile("cp.async.commit_group;")
#define CP_WAIT(n)   asm volatile("cp.async.wait_group %0;" :: "n"(n))

// ============================================================================
// R4 GEMM core (LDG+STS transpose staging, double-buffered). Scalar FFMA,
// strictly ascending-k per output element: numerics bitwise-frozen.
// Used by the fused x-GEMM (K=2048).
// ============================================================================
#define GEMM_STS(buf)                                                            \
    As[buf][ca0*4+0][r_a]=ra0.x; As[buf][ca0*4+1][r_a]=ra0.y;                    \
    As[buf][ca0*4+2][r_a]=ra0.z; As[buf][ca0*4+3][r_a]=ra0.w;                    \
    As[buf][ca0*4+4][r_a]=ra1.x; As[buf][ca0*4+5][r_a]=ra1.y;                    \
    As[buf][ca0*4+6][r_a]=ra1.z; As[buf][ca0*4+7][r_a]=ra1.w;                    \
    *(float4*)&Bs[buf][r_b][cb0*4]     = rb0;                                    \
    *(float4*)&Bs[buf][r_b][cb0*4 + 4] = rb1;

#define GEMM_LDG(k0)                                                             \
    {   const float* Ap = Abase + (k0);                                          \
        ra0 = *(const float4*)(Ap + ca0*4);                                      \
        ra1 = *(const float4*)(Ap + ca0*4 + 4);                                  \
        const float* Bp = (Bb) + (size_t)((k0) + r_b) * Nstride;                 \
        rb0 = *(const float4*)(Bp + cb0*4);                                      \
        rb1 = *(const float4*)(Bp + cb0*4 + 4);                                  \
    }

#define GEMM_PIPE(Ab, Bb, KDIM)                                                  \
    float acc[8][8];                                                             \
    _Pragma("unroll")                                                            \
    for (int i = 0; i < 8; i++)                                                  \
        _Pragma("unroll")                                                        \
        for (int j = 0; j < 8; j++) acc[i][j] = 0.0f;                            \
    const int r_a = tid >> 1, ca0 = (tid & 1) * 2;                               \
    const int r_b = tid >> 4, cb0 = (tid & 15) * 2;                              \
    const float* Abase = (Ab) + (size_t)r_a * (KDIM);                            \
    float4 ra0, ra1, rb0, rb1;                                                   \
    GEMM_LDG(0)                                                                  \
    GEMM_STS(0)                                                                  \
    __syncthreads();                                                             \
    const int ITERS = (KDIM) / 16;                                               \
    for (int it = 0; it < ITERS; it++) {                                         \
        const int cur = it & 1;                                                  \
        if (it + 1 < ITERS) { GEMM_LDG((it + 1) * 16) }                          \
        _Pragma("unroll")                                                        \
        for (int k = 0; k < 16; k++) {                                           \
            float a[8], b[8];                                                    \
            const float4* a4 = (const float4*)&As[cur][k][tm * 8];               \
            const float4* b4 = (const float4*)&Bs[cur][k][tn * 8];               \
            float4 av0 = a4[0], av1 = a4[1];                                     \
            float4 bv0 = b4[0], bv1 = b4[1];                                     \
            a[0]=av0.x; a[1]=av0.y; a[2]=av0.z; a[3]=av0.w;                      \
            a[4]=av1.x; a[5]=av1.y; a[6]=av1.z; a[7]=av1.w;                      \
            b[0]=bv0.x; b[1]=bv0.y; b[2]=bv0.z; b[3]=bv0.w;                      \
            b[4]=bv1.x; b[5]=bv1.y; b[6]=bv1.z; b[7]=bv1.w;                      \
            _Pragma("unroll")                                                    \
            for (int i = 0; i < 8; i++)                                          \
                _Pragma("unroll")                                                \
                for (int j = 0; j < 8; j++) acc[i][j] += a[i] * b[j];            \
        }                                                                        \
        if (it + 1 < ITERS) { GEMM_STS(cur ^ 1) }                                \
        __syncthreads();                                                         \
    }

// ---------------- fused Ws1 + W1c GEMM --------------------------------------
// bx in [0,8): h tile -> stored TRANSPOSED into g_hT.  bx == 8: c1 tile.
__global__ void __launch_bounds__(256, 2) sgemm_fused(
    const float* __restrict__ x,
    const float* __restrict__ Ws1, const float* __restrict__ bs1,
    const float* __restrict__ W1c, const float* __restrict__ b1c)
{
    __shared__ float As[2][16][128];
    __shared__ float Bs[2][16][128];
    const int bx = blockIdx.x, by = blockIdx.y;
    const int tid = threadIdx.x;
    const int tn = tid & 15, tm = tid >> 4;

    const bool is_c1 = (bx == 8);
    const float* Bsel = is_c1 ? W1c : Ws1;
    const float* bias = is_c1 ? b1c : bs1;
    const int Nstride = is_c1 ? 128 : HIDN;
    const int cb      = is_c1 ? 0 : bx * 128;

    const float* Ab = x + (size_t)by * 128 * IN_DIM;
    const float* Bb = Bsel + cb;

    GEMM_PIPE(Ab, Bb, IN_DIM)

    const float4 bi0 = *(const float4*)&bias[tn * 8];
    const float4 bi1 = *(const float4*)&bias[tn * 8 + 4];
    float r_[8][8];
#pragma unroll
    for (int i = 0; i < 8; i++) {
        r_[i][0] = fmaxf(__fadd_rn(acc[i][0], bi0.x), 0.0f);
        r_[i][1] = fmaxf(__fadd_rn(acc[i][1], bi0.y), 0.0f);
        r_[i][2] = fmaxf(__fadd_rn(acc[i][2], bi0.z), 0.0f);
        r_[i][3] = fmaxf(__fadd_rn(acc[i][3], bi0.w), 0.0f);
        r_[i][4] = fmaxf(__fadd_rn(acc[i][4], bi1.x), 0.0f);
        r_[i][5] = fmaxf(__fadd_rn(acc[i][5], bi1.y), 0.0f);
        r_[i][6] = fmaxf(__fadd_rn(acc[i][6], bi1.z), 0.0f);
        r_[i][7] = fmaxf(__fadd_rn(acc[i][7], bi1.w), 0.0f);
    }
    const int row0 = by * 128 + tm * 8;
    if (!is_c1) {
        // transposed store: g_hT[col][row]
#pragma unroll
        for (int j = 0; j < 8; j++) {
            const int col = cb + tn * 8 + j;
            float4 lo = make_float4(r_[0][j], r_[1][j], r_[2][j], r_[3][j]);
            float4 hi = make_float4(r_[4][j], r_[5][j], r_[6][j], r_[7][j]);
            float* cp = g_hT + (size_t)col * BATCH + row0;
            *(float4*)cp = lo;
            *(float4*)(cp + 4) = hi;
        }
    } else {
#pragma unroll
        for (int i = 0; i < 8; i++) {
            float* cp = g_c1 + (size_t)(row0 + i) * 128 + tn * 8;
            *(float4*)cp = make_float4(r_[i][0], r_[i][1], r_[i][2], r_[i][3]);
            *(float4*)(cp + 4) = make_float4(r_[i][4], r_[i][5], r_[i][6], r_[i][7]);
        }
    }
}

// ============================================================================
// scores GEMM: cp.async 3-stage ring + frag ping-pong, conflict-free B frags.
// A = hT [HIDN][BATCH] (k-major), B = Ws2 [HIDN][POOLN] (k-major).
// Thread (tm,tn) owns rows tm*8..+7, cols {tn*4..+3} and {64+tn*4..+3}.
// acc[i][j] accumulates ascending k -> scores bitwise identical.
// ============================================================================
#define FRAG_LD2(av, bv, buf, k)                                                 \
    {   const float4* a4 = (const float4*)&As[buf][k][tm * 8];                   \
        float4 t0 = a4[0], t1 = a4[1];                                           \
        float4 t2 = *(const float4*)&Bs[buf][k][tn * 4];                         \
        float4 t3 = *(const float4*)&Bs[buf][k][64 + tn * 4];                    \
        av[0]=t0.x; av[1]=t0.y; av[2]=t0.z; av[3]=t0.w;                          \
        av[4]=t1.x; av[5]=t1.y; av[6]=t1.z; av[7]=t1.w;                          \
        bv[0]=t2.x; bv[1]=t2.y; bv[2]=t2.z; bv[3]=t2.w;                          \
        bv[4]=t3.x; bv[5]=t3.y; bv[6]=t3.z; bv[7]=t3.w;                          \
    }

#define FMA_BLOCK(av, bv)                                                        \
    _Pragma("unroll")                                                            \
    for (int i = 0; i < 8; i++)                                                  \
        _Pragma("unroll")                                                        \
        for (int j = 0; j < 8; j++) acc[i][j] += av[i] * bv[j];

__global__ void __launch_bounds__(256, 1) sgemm_scores_ca(
    const float* __restrict__ AT, const float* __restrict__ B,
    const float* __restrict__ bias, const float* __restrict__ noise,
    float* __restrict__ C)
{
    __shared__ float As[3][16][128];
    __shared__ float Bs[3][16][128];
    const int bx = blockIdx.x, by = blockIdx.y;
    const int tid = threadIdx.x;
    const int tn = tid & 15, tm = tid >> 4;

    // copy mapping: each thread copies 32B at (row r_c, float col cc) per tile
    const int r_c = tid >> 4;          // 0..15
    const int cc  = (tid & 15) * 8;    // 0..120

    const float* gA = AT + (size_t)r_c * BATCH + by * 128 + cc;
    const float* gB = B  + (size_t)r_c * POOLN + bx * 128 + cc;
    const size_t stepA = (size_t)16 * BATCH;
    const size_t stepB = (size_t)16 * POOLN;

#define CPA_TILE(buf)                                                            \
    {   float* dA = &As[buf][r_c][cc];                                           \
        cpa16(dA, gA); cpa16(dA + 4, gA + 4);                                    \
        float* dB = &Bs[buf][r_c][cc];                                           \
        cpa16(dB, gB); cpa16(dB + 4, gB + 4);                                    \
        CP_COMMIT();                                                             \
        gA += stepA; gB += stepB; }

    float acc[8][8];
#pragma unroll
    for (int i = 0; i < 8; i++)
#pragma unroll
        for (int j = 0; j < 8; j++) acc[i][j] = 0.0f;

    CPA_TILE(0)
    CPA_TILE(1)

    float af0[8], af1[8], bf0[8], bf1[8];
    const int ITERS = HIDN / 16;   // 64
    for (int it = 0; it < ITERS; it++) {
        const int cur = it % 3;
        CP_WAIT(1);                 // tile `it` landed (own thread's portion)
        __syncthreads();            // everyone's portion visible
        FRAG_LD2(af0, bf0, cur, 0)
#pragma unroll
        for (int k = 0; k < 15; k++) {
            if (k & 1) { FRAG_LD2(af0, bf0, cur, k + 1) FMA_BLOCK(af1, bf1) }
            else       { FRAG_LD2(af1, bf1, cur, k + 1) FMA_BLOCK(af0, bf0) }
        }
        if (it + 2 < ITERS) { CPA_TILE((it + 2) % 3) }
        else                { CP_COMMIT(); }     // keep group parity for CP_WAIT(1)
        FMA_BLOCK(af1, bf1)         // k = 15
    }

    const int colL = bx * 128 + tn * 4;      // j 0..3
    const int colH = colL + 64;              // j 4..7
    const float4 biL = *(const float4*)&bias[colL];
    const float4 biH = *(const float4*)&bias[colH];
#pragma unroll
    for (int i = 0; i < 8; i++) {
        const int row = by * 128 + tm * 8 + i;
        const float* np = noise + (size_t)row * POOLN;
        float4 nL = *(const float4*)(np + colL);
        float4 nH = *(const float4*)(np + colH);
        float4 oL, oH;
        oL.x = __fadd_rn(__fadd_rn(acc[i][0], biL.x), __fmul_rn(nL.x, 0.1f));
        oL.y = __fadd_rn(__fadd_rn(acc[i][1], biL.y), __fmul_rn(nL.y, 0.1f));
        oL.z = __fadd_rn(__fadd_rn(acc[i][2], biL.z), __fmul_rn(nL.z, 0.1f));
        oL.w = __fadd_rn(__fadd_rn(acc[i][3], biL.w), __fmul_rn(nL.w, 0.1f));
        oH.x = __fadd_rn(__fadd_rn(acc[i][4], biH.x), __fmul_rn(nH.x, 0.1f));
        oH.y = __fadd_rn(__fadd_rn(acc[i][5], biH.y), __fmul_rn(nH.y, 0.1f));
        oH.z = __fadd_rn(__fadd_rn(acc[i][6], biH.z), __fmul_rn(nH.z, 0.1f));
        oH.w = __fadd_rn(__fadd_rn(acc[i][7], biH.w), __fmul_rn(nH.w, 0.1f));
        float* cp = C + (size_t)row * POOLN;
        *(float4*)(cp + colL) = oL;
        *(float4*)(cp + colH) = oH;
    }
}

// ---------------- comp stage 2: sigmoid(c1 @ W2c + b2c) ---------------------
__global__ void comp_kernel(const float* __restrict__ W2c,
                            const float* __restrict__ b2c,
                            float* __restrict__ out_comp)
{
    int row  = blockIdx.x * 8 + (threadIdx.x >> 5);
    int lane = threadIdx.x & 31;
    float p = 0.0f;
#pragma unroll
    for (int t = lane; t < 128; t += 32) p += g_c1[row * 128 + t] * W2c[t];
#pragma unroll
    for (int o = 16; o > 0; o >>= 1) p += __shfl_down_sync(0xffffffffu, p, o);
    if (lane == 0) {
        float z = p + b2c[0];
        float c = 1.0f / (1.0f + expf(-z));
        g_comp[row]  = c;
        out_comp[row] = c;
    }
}

// ---------------- budget ----------------------------------------------------
__global__ void budget_kernel(float* __restrict__ out_budget)
{
    __shared__ float ws[32];
    int tid = threadIdx.x;
    float s = g_comp[tid] + g_comp[tid + 1024];
#pragma unroll
    for (int o = 16; o > 0; o >>= 1) s += __shfl_down_sync(0xffffffffu, s, o);
    if ((tid & 31) == 0) ws[tid >> 5] = s;
    __syncthreads();
    if (tid < 32) {
        float v = ws[tid];
#pragma unroll
        for (int o = 16; o > 0; o >>= 1) v += __shfl_down_sync(0xffffffffu, v, o);
        if (tid == 0) {
            float mean  = v / 2048.0f;
            float scale = mean * mean;                 // EXP = 2.0
            float t = 512.0f + 7680.0f * scale;
            int b = (int)floorf(t);
            if (b < MINP) b = MINP;
            if (b > MAXP) b = MAXP;
            g_budget = b;
            out_budget[0] = (float)b;
        }
    }
}

// ============================================================================
// top-k + softmax  (unchanged)
// ============================================================================
__device__ __forceinline__ unsigned f2key(float s) {
    unsigned b = __float_as_uint(s);
    return (b & 0x80000000u) ? ~b : (b | 0x80000000u);   // order-preserving
}
__device__ __forceinline__ float key2f(unsigned k) {
    return __uint_as_float((k & 0x80000000u) ? (k ^ 0x80000000u) : ~k);
}

#define OFF_KEYS   0
#define OFF_SBUFA  131072
#define OFF_HIST   196608
#define OFF_RED    212992
#define TOPK_SMEM  (212992 + 640)

__device__ __forceinline__ u32 scan4096(u32* a, u32* red, int tid,
                                        u32 h[4], u32 ex[4])
{
    const int lane = tid & 31, warp = tid >> 5;
#pragma unroll
    for (int i = 0; i < 4; i++) h[i] = a[tid * 4 + i];
    u32 s = h[0] + h[1] + h[2] + h[3];
    u32 inc = s;
#pragma unroll
    for (int o = 1; o < 32; o <<= 1) {
        u32 n = __shfl_up_sync(0xffffffffu, inc, o);
        if (lane >= o) inc += n;
    }
    if (lane == 31) red[warp] = inc;
    __syncthreads();
    if (tid < 32) {
        u32 v = red[tid];
#pragma unroll
        for (int o = 1; o < 32; o <<= 1) {
            u32 n = __shfl_up_sync(0xffffffffu, v, o);
            if (tid >= o) v += n;
        }
        red[32 + tid] = v;
    }
    __syncthreads();
    u32 wb = (warp == 0) ? 0u : red[32 + warp - 1];
    u32 tb = wb + inc - s;
    ex[0] = tb; ex[1] = ex[0] + h[0]; ex[2] = ex[1] + h[1]; ex[3] = ex[2] + h[2];
#pragma unroll
    for (int i = 0; i < 4; i++) a[tid * 4 + i] = ex[i];
    u32 total = red[32 + 31];
    __syncthreads();
    return total;
}

__device__ __forceinline__ unsigned eqmask4(unsigned d) {
    unsigned m = 0xffffffffu;
#pragma unroll
    for (int b = 0; b < 4; b++) {
        unsigned bal = __ballot_sync(0xffffffffu, (d >> b) & 1u);
        m &= ((d >> b) & 1u) ? bal : ~bal;
    }
    return m;
}

__global__ void __launch_bounds__(1024) topk_kernel(
    float* __restrict__ out_idx, float* __restrict__ out_w)
{
    extern __shared__ unsigned char smem_raw[];
    u32* keys  = (u32*)(smem_raw + OFF_KEYS);
    u64* sbufA = (u64*)(smem_raw + OFF_SBUFA);
    u64* sbufB = (u64*)(smem_raw + OFF_KEYS);     // alias: valid after keys dead
    u32* hist  = (u32*)(smem_raw + OFF_HIST);
    u32* red   = (u32*)(smem_raw + OFF_RED);
    float* fred = (float*)red;

    const int row = blockIdx.x;
    const int tid = threadIdx.x;
    const int warp = tid >> 5, lane = tid & 31;
    const unsigned ltm = (1u << lane) - 1u;
    const float* srow = g_scores + (size_t)row * POOLN;

    for (int j = tid; j < POOLN; j += 1024) keys[j] = f2key(srow[j]);
    __syncthreads();

    // ---- exact k-th largest key via 3-level radix histogram (12/12/8) ----
    unsigned prefix = 0;
    u32 base_gt = 0;
#pragma unroll
    for (int lvl = 0; lvl < 3; lvl++) {
        const int lb   = (lvl < 2) ? 12 : 8;
        const int done = (lvl == 0) ? 0 : (lvl == 1 ? 12 : 24);
#pragma unroll
        for (int i = 0; i < 4; i++) hist[tid * 4 + i] = 0;
        __syncthreads();
        for (int j = tid; j < POOLN; j += 1024) {
            u32 k = keys[j];
            bool part = (done == 0) || ((k >> (32 - done)) == prefix);
            unsigned d = part ? ((k << done) >> (32 - lb)) : 0xFFFFFFFFu;
            unsigned m = __match_any_sync(0xffffffffu, d);
            if (part && (m & ltm) == 0)
                atomicAdd(&hist[d], __popc(m));
        }
        __syncthreads();
        u32 h4[4], ex4[4];
        u32 T = scan4096(hist, red, tid, h4, ex4);
#pragma unroll
        for (int i = 0; i < 4; i++) {
            u32 cg = T - ex4[i] - h4[i];
            if (h4[i] && base_gt + cg < MAXP && base_gt + cg + h4[i] >= MAXP) {
                red[140] = (u32)(tid * 4 + i);
                red[141] = cg;
            }
        }
        __syncthreads();
        prefix = (prefix << lb) | red[140];
        base_gt += red[141];
        __syncthreads();
    }
    const unsigned V = prefix;

    // ---- stable compaction ----
    const int beg = tid * 32;
    int cgt = 0, ceq = 0;
#pragma unroll 8
    for (int j = beg; j < beg + 32; j++) {
        unsigned k = keys[j];
        cgt += (k > V); ceq += (k == V);
    }
    int vg = cgt, ve = ceq;
#pragma unroll
    for (int o = 1; o < 32; o <<= 1) {
        int ng = __shfl_up_sync(0xffffffffu, vg, o);
        int ne = __shfl_up_sync(0xffffffffu, ve, o);
        if (lane >= o) { vg += ng; ve += ne; }
    }
    if (lane == 31) { red[2 + warp] = (u32)vg; red[34 + warp] = (u32)ve; }
    __syncthreads();
    if (tid < 32) {
        int wg = (int)red[2 + tid], we = (int)red[34 + tid];
#pragma unroll
        for (int o = 1; o < 32; o <<= 1) {
            int ng = __shfl_up_sync(0xffffffffu, wg, o);
            int ne = __shfl_up_sync(0xffffffffu, we, o);
            if (tid >= o) { wg += ng; we += ne; }
        }
        red[2 + tid] = (u32)wg; red[34 + tid] = (u32)we;
    }
    __syncthreads();
    int bgt = vg - cgt + (warp ? (int)red[2 + warp - 1] : 0);
    int beq = ve - ceq + (warp ? (int)red[34 + warp - 1] : 0);
    const int count_gt = (int)red[2 + 31];
    const int need_eq  = MAXP - count_gt;

    for (int j = beg; j < beg + 32; j++) {
        unsigned k = keys[j];
        if (k > V) {
            sbufA[bgt++] = ((u64)(~k) << 32) | (unsigned)j;
        } else if (k == V) {
            int r = beq++;
            if (r < need_eq)
                sbufA[count_gt + r] = ((u64)(~V) << 32) | (unsigned)j;
        }
    }
    __syncthreads();

    // ---- stable LSD radix sort: 8 x 4-bit on ~key ----
    u64* src = sbufA;
    u64* dst = sbufB;
#pragma unroll 1
    for (int p = 0; p < 8; p++) {
        const int shift = 32 + 4 * p;
#pragma unroll
        for (int i = 0; i < 4; i++) hist[tid * 4 + i] = 0;
        __syncthreads();
#pragma unroll 1
        for (int e = 0; e < 8; e++) {
            u64 v = src[e * 1024 + tid];
            unsigned d = (unsigned)(v >> shift) & 15u;
            unsigned m = eqmask4(d);
            if ((m & ltm) == 0)
                hist[d * 256 + e * 32 + warp] = (u32)__popc(m);
        }
        __syncthreads();
        u32 h4[4], ex4[4];
        scan4096(hist, red, tid, h4, ex4);
#pragma unroll 1
        for (int e = 0; e < 8; e++) {
            u64 v = src[e * 1024 + tid];
            unsigned d = (unsigned)(v >> shift) & 15u;
            unsigned m = eqmask4(d);
            unsigned rk = (unsigned)__popc(m & ltm);
            dst[hist[d * 256 + e * 32 + warp] + rk] = v;
        }
        __syncthreads();
        u64* t = src; src = dst; dst = t;
    }

    // ---- softmax over first `budget` entries ----
    const float s0 = key2f(~(unsigned)(src[0] >> 32));
    const int budget = g_budget;
    float part = 0.0f;
    float ev[8]; int iv[8];
#pragma unroll
    for (int i = 0; i < 8; i++) {
        int pp = tid + i * 1024;
        u64 v = src[pp];
        unsigned key = ~(unsigned)(v >> 32);
        iv[i] = (int)(v & 0xFFFFFFFFu);
        float e = (pp < budget) ? expf(key2f(key) - s0) : 0.0f;
        ev[i] = e;
        part += e;
    }
#pragma unroll
    for (int o = 16; o > 0; o >>= 1) part += __shfl_down_sync(0xffffffffu, part, o);
    __syncthreads();
    if (lane == 0) fred[64 + warp] = part;
    __syncthreads();
    if (tid == 0) {
        float s = 0.0f;
        for (int w = 0; w < 32; w++) s += fred[64 + w];
        fred[96] = s;
    }
    __syncthreads();
    const float denom = fred[96];

#pragma unroll
    for (int i = 0; i < 8; i++) {
        int pp = tid + i * 1024;
        out_idx[(size_t)row * MAXP + pp] = (float)iv[i];
        out_w  [(size_t)row * MAXP + pp] = ev[i] / denom;
    }
}

// ---------------- launch -----------------------------------------------------
extern "C" void kernel_launch(void* const* d_in, const int* in_sizes, int n_in,
                              void* d_out, int out_size)
{
    const float* x    = (const float*)d_in[0];
    const float* noise= (const float*)d_in[1];
    const float* W1c  = (const float*)d_in[2];
    const float* b1c  = (const float*)d_in[3];
    const float* W2c  = (const float*)d_in[4];
    const float* b2c  = (const float*)d_in[5];
    const float* Ws1  = (const float*)d_in[6];
    const float* bs1  = (const float*)d_in[7];
    const float* Ws2  = (const float*)d_in[8];
    const float* bs2  = (const float*)d_in[9];

    float* out        = (float*)d_out;
    float* out_idx    = out;
    float* out_budget = out + (size_t)BATCH * MAXP;
    float* out_w      = out_budget + 1;
    float* out_comp   = out_w + (size_t)BATCH * MAXP;

    float *hTp, *sp;
    cudaGetSymbolAddress((void**)&hTp, g_hT);
    cudaGetSymbolAddress((void**)&sp,  g_scores);

    // fused: hT = relu(x@Ws1+bs1)^T  and  c1 = relu(x@W1c+b1c)  in one wave
    sgemm_fused<<<dim3(9, 16), 256>>>(x, Ws1, bs1, W1c, b1c);
    comp_kernel<<<256, 256>>>(W2c, b2c, out_comp);
    budget_kernel<<<1, 1024>>>(out_budget);

    // scores = h@Ws2 + bs2 + noise*0.1   (A = hT, both operands k-major)
    sgemm_scores_ca<<<dim3(256, 16), 256>>>(hTp, Ws2, bs2, noise, sp);

    // top-k + softmax
    cudaFuncSetAttribute(topk_kernel, cudaFuncAttributeMaxDynamicSharedMemorySize, TOPK_SMEM);
    topk_kernel<<<BATCH, 1024, TOPK_SMEM>>>(out_idx, out_w);
}

// round 8
// speedup vs baseline: 1.2046x; 1.0894x over previous
#include <cuda_runtime.h>
#include <math.h>
#include <stdint.h>

#define BATCH    2048
#define IN_DIM   2048
#define POOLN    32768
#define HIDN     1024
#define MAXP     8192
#define MINP     512

typedef unsigned long long u64;
typedef unsigned int u32;
typedef unsigned short u16;

// ---------------- scratch (device globals: no allocations allowed) ----------
__device__ float g_c1[BATCH * 128];
__device__ float g_hT[(size_t)HIDN * BATCH];        // h transposed: [k][row]
__device__ float g_scores[(size_t)BATCH * POOLN];   // 256 MB
__device__ float g_comp[BATCH];
__device__ int   g_budget;

// ---------------- cp.async helpers ------------------------------------------
__device__ __forceinline__ void cpa16(void* smem, const void* gmem) {
    unsigned s = (unsigned)__cvta_generic_to_shared(smem);
    asm volatile("cp.async.cg.shared.global [%0], [%1], 16;" :: "r"(s), "l"(gmem));
}
#define CP_COMMIT()  asm volatile("cp.async.commit_group;")
#define CP_WAIT(n)   asm volatile("cp.async.wait_group %0;" :: "n"(n))

// ============================================================================
// fused x-GEMM core (unchanged from R7)
// ============================================================================
#define GEMM_STS(buf)                                                            \
    As[buf][ca0*4+0][r_a]=ra0.x; As[buf][ca0*4+1][r_a]=ra0.y;                    \
    As[buf][ca0*4+2][r_a]=ra0.z; As[buf][ca0*4+3][r_a]=ra0.w;                    \
    As[buf][ca0*4+4][r_a]=ra1.x; As[buf][ca0*4+5][r_a]=ra1.y;                    \
    As[buf][ca0*4+6][r_a]=ra1.z; As[buf][ca0*4+7][r_a]=ra1.w;                    \
    *(float4*)&Bs[buf][r_b][cb0*4]     = rb0;                                    \
    *(float4*)&Bs[buf][r_b][cb0*4 + 4] = rb1;

#define GEMM_LDG(k0)                                                             \
    {   const float* Ap = Abase + (k0);                                          \
        ra0 = *(const float4*)(Ap + ca0*4);                                      \
        ra1 = *(const float4*)(Ap + ca0*4 + 4);                                  \
        const float* Bp = (Bb) + (size_t)((k0) + r_b) * Nstride;                 \
        rb0 = *(const float4*)(Bp + cb0*4);                                      \
        rb1 = *(const float4*)(Bp + cb0*4 + 4);                                  \
    }

#define GEMM_PIPE(Ab, Bb, KDIM)                                                  \
    float acc[8][8];                                                             \
    _Pragma("unroll")                                                            \
    for (int i = 0; i < 8; i++)                                                  \
        _Pragma("unroll")                                                        \
        for (int j = 0; j < 8; j++) acc[i][j] = 0.0f;                            \
    const int r_a = tid >> 1, ca0 = (tid & 1) * 2;                               \
    const int r_b = tid >> 4, cb0 = (tid & 15) * 2;                              \
    const float* Abase = (Ab) + (size_t)r_a * (KDIM);                            \
    float4 ra0, ra1, rb0, rb1;                                                   \
    GEMM_LDG(0)                                                                  \
    GEMM_STS(0)                                                                  \
    __syncthreads();                                                             \
    const int ITERS = (KDIM) / 16;                                               \
    for (int it = 0; it < ITERS; it++) {                                         \
        const int cur = it & 1;                                                  \
        if (it + 1 < ITERS) { GEMM_LDG((it + 1) * 16) }                          \
        _Pragma("unroll")                                                        \
        for (int k = 0; k < 16; k++) {                                           \
            float a[8], b[8];                                                    \
            const float4* a4 = (const float4*)&As[cur][k][tm * 8];               \
            const float4* b4 = (const float4*)&Bs[cur][k][tn * 8];               \
            float4 av0 = a4[0], av1 = a4[1];                                     \
            float4 bv0 = b4[0], bv1 = b4[1];                                     \
            a[0]=av0.x; a[1]=av0.y; a[2]=av0.z; a[3]=av0.w;                      \
            a[4]=av1.x; a[5]=av1.y; a[6]=av1.z; a[7]=av1.w;                      \
            b[0]=bv0.x; b[1]=bv0.y; b[2]=bv0.z; b[3]=bv0.w;                      \
            b[4]=bv1.x; b[5]=bv1.y; b[6]=bv1.z; b[7]=bv1.w;                      \
            _Pragma("unroll")                                                    \
            for (int i = 0; i < 8; i++)                                          \
                _Pragma("unroll")                                                \
                for (int j = 0; j < 8; j++) acc[i][j] += a[i] * b[j];            \
        }                                                                        \
        if (it + 1 < ITERS) { GEMM_STS(cur ^ 1) }                                \
        __syncthreads();                                                         \
    }

__global__ void __launch_bounds__(256, 2) sgemm_fused(
    const float* __restrict__ x,
    const float* __restrict__ Ws1, const float* __restrict__ bs1,
    const float* __restrict__ W1c, const float* __restrict__ b1c)
{
    __shared__ float As[2][16][128];
    __shared__ float Bs[2][16][128];
    const int bx = blockIdx.x, by = blockIdx.y;
    const int tid = threadIdx.x;
    const int tn = tid & 15, tm = tid >> 4;

    const bool is_c1 = (bx == 8);
    const float* Bsel = is_c1 ? W1c : Ws1;
    const float* bias = is_c1 ? b1c : bs1;
    const int Nstride = is_c1 ? 128 : HIDN;
    const int cb      = is_c1 ? 0 : bx * 128;

    const float* Ab = x + (size_t)by * 128 * IN_DIM;
    const float* Bb = Bsel + cb;

    GEMM_PIPE(Ab, Bb, IN_DIM)

    const float4 bi0 = *(const float4*)&bias[tn * 8];
    const float4 bi1 = *(const float4*)&bias[tn * 8 + 4];
    float r_[8][8];
#pragma unroll
    for (int i = 0; i < 8; i++) {
        r_[i][0] = fmaxf(__fadd_rn(acc[i][0], bi0.x), 0.0f);
        r_[i][1] = fmaxf(__fadd_rn(acc[i][1], bi0.y), 0.0f);
        r_[i][2] = fmaxf(__fadd_rn(acc[i][2], bi0.z), 0.0f);
        r_[i][3] = fmaxf(__fadd_rn(acc[i][3], bi0.w), 0.0f);
        r_[i][4] = fmaxf(__fadd_rn(acc[i][4], bi1.x), 0.0f);
        r_[i][5] = fmaxf(__fadd_rn(acc[i][5], bi1.y), 0.0f);
        r_[i][6] = fmaxf(__fadd_rn(acc[i][6], bi1.z), 0.0f);
        r_[i][7] = fmaxf(__fadd_rn(acc[i][7], bi1.w), 0.0f);
    }
    const int row0 = by * 128 + tm * 8;
    if (!is_c1) {
#pragma unroll
        for (int j = 0; j < 8; j++) {
            const int col = cb + tn * 8 + j;
            float4 lo = make_float4(r_[0][j], r_[1][j], r_[2][j], r_[3][j]);
            float4 hi = make_float4(r_[4][j], r_[5][j], r_[6][j], r_[7][j]);
            float* cp = g_hT + (size_t)col * BATCH + row0;
            *(float4*)cp = lo;
            *(float4*)(cp + 4) = hi;
        }
    } else {
#pragma unroll
        for (int i = 0; i < 8; i++) {
            float* cp = g_c1 + (size_t)(row0 + i) * 128 + tn * 8;
            *(float4*)cp = make_float4(r_[i][0], r_[i][1], r_[i][2], r_[i][3]);
            *(float4*)(cp + 4) = make_float4(r_[i][4], r_[i][5], r_[i][6], r_[i][7]);
        }
    }
}

// ============================================================================
// scores GEMM (unchanged from R7)
// ============================================================================
#define FRAG_LD2(av, bv, buf, k)                                                 \
    {   const float4* a4 = (const float4*)&As[buf][k][tm * 8];                   \
        float4 t0 = a4[0], t1 = a4[1];                                           \
        float4 t2 = *(const float4*)&Bs[buf][k][tn * 4];                         \
        float4 t3 = *(const float4*)&Bs[buf][k][64 + tn * 4];                    \
        av[0]=t0.x; av[1]=t0.y; av[2]=t0.z; av[3]=t0.w;                          \
        av[4]=t1.x; av[5]=t1.y; av[6]=t1.z; av[7]=t1.w;                          \
        bv[0]=t2.x; bv[1]=t2.y; bv[2]=t2.z; bv[3]=t2.w;                          \
        bv[4]=t3.x; bv[5]=t3.y; bv[6]=t3.z; bv[7]=t3.w;                          \
    }

#define FMA_BLOCK(av, bv)                                                        \
    _Pragma("unroll")                                                            \
    for (int i = 0; i < 8; i++)                                                  \
        _Pragma("unroll")                                                        \
        for (int j = 0; j < 8; j++) acc[i][j] += av[i] * bv[j];

__global__ void __launch_bounds__(256, 1) sgemm_scores_ca(
    const float* __restrict__ AT, const float* __restrict__ B,
    const float* __restrict__ bias, const float* __restrict__ noise,
    float* __restrict__ C)
{
    __shared__ float As[3][16][128];
    __shared__ float Bs[3][16][128];
    const int bx = blockIdx.x, by = blockIdx.y;
    const int tid = threadIdx.x;
    const int tn = tid & 15, tm = tid >> 4;

    const int r_c = tid >> 4;
    const int cc  = (tid & 15) * 8;

    const float* gA = AT + (size_t)r_c * BATCH + by * 128 + cc;
    const float* gB = B  + (size_t)r_c * POOLN + bx * 128 + cc;
    const size_t stepA = (size_t)16 * BATCH;
    const size_t stepB = (size_t)16 * POOLN;

#define CPA_TILE(buf)                                                            \
    {   float* dA = &As[buf][r_c][cc];                                           \
        cpa16(dA, gA); cpa16(dA + 4, gA + 4);                                    \
        float* dB = &Bs[buf][r_c][cc];                                           \
        cpa16(dB, gB); cpa16(dB + 4, gB + 4);                                    \
        CP_COMMIT();                                                             \
        gA += stepA; gB += stepB; }

    float acc[8][8];
#pragma unroll
    for (int i = 0; i < 8; i++)
#pragma unroll
        for (int j = 0; j < 8; j++) acc[i][j] = 0.0f;

    CPA_TILE(0)
    CPA_TILE(1)

    float af0[8], af1[8], bf0[8], bf1[8];
    const int ITERS = HIDN / 16;
    for (int it = 0; it < ITERS; it++) {
        const int cur = it % 3;
        CP_WAIT(1);
        __syncthreads();
        FRAG_LD2(af0, bf0, cur, 0)
#pragma unroll
        for (int k = 0; k < 15; k++) {
            if (k & 1) { FRAG_LD2(af0, bf0, cur, k + 1) FMA_BLOCK(af1, bf1) }
            else       { FRAG_LD2(af1, bf1, cur, k + 1) FMA_BLOCK(af0, bf0) }
        }
        if (it + 2 < ITERS) { CPA_TILE((it + 2) % 3) }
        else                { CP_COMMIT(); }
        FMA_BLOCK(af1, bf1)
    }

    const int colL = bx * 128 + tn * 4;
    const int colH = colL + 64;
    const float4 biL = *(const float4*)&bias[colL];
    const float4 biH = *(const float4*)&bias[colH];
#pragma unroll
    for (int i = 0; i < 8; i++) {
        const int row = by * 128 + tm * 8 + i;
        const float* np = noise + (size_t)row * POOLN;
        float4 nL = *(const float4*)(np + colL);
        float4 nH = *(const float4*)(np + colH);
        float4 oL, oH;
        oL.x = __fadd_rn(__fadd_rn(acc[i][0], biL.x), __fmul_rn(nL.x, 0.1f));
        oL.y = __fadd_rn(__fadd_rn(acc[i][1], biL.y), __fmul_rn(nL.y, 0.1f));
        oL.z = __fadd_rn(__fadd_rn(acc[i][2], biL.z), __fmul_rn(nL.z, 0.1f));
        oL.w = __fadd_rn(__fadd_rn(acc[i][3], biL.w), __fmul_rn(nL.w, 0.1f));
        oH.x = __fadd_rn(__fadd_rn(acc[i][4], biH.x), __fmul_rn(nH.x, 0.1f));
        oH.y = __fadd_rn(__fadd_rn(acc[i][5], biH.y), __fmul_rn(nH.y, 0.1f));
        oH.z = __fadd_rn(__fadd_rn(acc[i][6], biH.z), __fmul_rn(nH.z, 0.1f));
        oH.w = __fadd_rn(__fadd_rn(acc[i][7], biH.w), __fmul_rn(nH.w, 0.1f));
        float* cp = C + (size_t)row * POOLN;
        *(float4*)(cp + colL) = oL;
        *(float4*)(cp + colH) = oH;
    }
}

// ---------------- comp stage 2 / budget (unchanged) --------------------------
__global__ void comp_kernel(const float* __restrict__ W2c,
                            const float* __restrict__ b2c,
                            float* __restrict__ out_comp)
{
    int row  = blockIdx.x * 8 + (threadIdx.x >> 5);
    int lane = threadIdx.x & 31;
    float p = 0.0f;
#pragma unroll
    for (int t = lane; t < 128; t += 32) p += g_c1[row * 128 + t] * W2c[t];
#pragma unroll
    for (int o = 16; o > 0; o >>= 1) p += __shfl_down_sync(0xffffffffu, p, o);
    if (lane == 0) {
        float z = p + b2c[0];
        float c = 1.0f / (1.0f + expf(-z));
        g_comp[row]  = c;
        out_comp[row] = c;
    }
}

__global__ void budget_kernel(float* __restrict__ out_budget)
{
    __shared__ float ws[32];
    int tid = threadIdx.x;
    float s = g_comp[tid] + g_comp[tid + 1024];
#pragma unroll
    for (int o = 16; o > 0; o >>= 1) s += __shfl_down_sync(0xffffffffu, s, o);
    if ((tid & 31) == 0) ws[tid >> 5] = s;
    __syncthreads();
    if (tid < 32) {
        float v = ws[tid];
#pragma unroll
        for (int o = 16; o > 0; o >>= 1) v += __shfl_down_sync(0xffffffffu, v, o);
        if (tid == 0) {
            float mean  = v / 2048.0f;
            float scale = mean * mean;
            float t = 512.0f + 7680.0f * scale;
            int b = (int)floorf(t);
            if (b < MINP) b = MINP;
            if (b > MAXP) b = MAXP;
            g_budget = b;
            out_budget[0] = (float)b;
        }
    }
}

// ============================================================================
// top-k + softmax — 512 threads, 2 CTAs/SM, selection from global,
// split key(u32)/idx(u16) stable LSD radix sort with register ranks.
// ============================================================================
__device__ __forceinline__ unsigned f2key(float s) {
    unsigned b = __float_as_uint(s);
    return (b & 0x80000000u) ? ~b : (b | 0x80000000u);
}
__device__ __forceinline__ float key2f(unsigned k) {
    return __uint_as_float((k & 0x80000000u) ? (k ^ 0x80000000u) : ~k);
}
__device__ __forceinline__ u32 rec4(u32 b0, u32 b1, u32 b2, u32 b3, u32 d) {
    u32 m = (d & 1u) ? b0 : ~b0;
    m &= (d & 2u) ? b1 : ~b1;
    m &= (d & 4u) ? b2 : ~b2;
    m &= (d & 8u) ? b3 : ~b3;
    return m;
}

// smem layout (bytes):
#define OFF_KEYA   0                    // u32[8192]  32KB
#define OFF_KEYB   32768                // u32[8192]  32KB (sel-hist aliases here)
#define OFF_IDXA   65536                // u16[8192]  16KB
#define OFF_IDXB   81920                // u16[8192]  16KB
#define OFF_SHIST  98304                // u32[2048]   8KB
#define OFF_RED    106496               // u32[96]
#define TOPK_SMEM  (106496 + 384)

__global__ void __launch_bounds__(512, 2) topk_kernel(
    float* __restrict__ out_idx, float* __restrict__ out_w)
{
    extern __shared__ unsigned char smem_raw[];
    u32* keyA    = (u32*)(smem_raw + OFF_KEYA);
    u32* keyB    = (u32*)(smem_raw + OFF_KEYB);
    u16* idxA    = (u16*)(smem_raw + OFF_IDXA);
    u16* idxB    = (u16*)(smem_raw + OFF_IDXB);
    u32* shist   = (u32*)(smem_raw + OFF_SHIST);
    u32* selhist = (u32*)(smem_raw + OFF_KEYB);   // alias, dead before sort
    u32* red     = (u32*)(smem_raw + OFF_RED);
    float* fred  = (float*)red;

    const int row = blockIdx.x;
    const int tid = threadIdx.x;
    const int w   = tid >> 5, lane = tid & 31;
    const unsigned ltm = (1u << lane) - 1u;
    const float* srow = g_scores + (size_t)row * POOLN;

    // ---- selection: exact k-th key via 3-level radix hist (12/12/8) --------
    unsigned prefix = 0;
    u32 base_gt = 0;
#pragma unroll 1
    for (int lvl = 0; lvl < 3; lvl++) {
        const int lb   = (lvl < 2) ? 12 : 8;
        const int done = (lvl == 0) ? 0 : (lvl == 1 ? 12 : 24);
#pragma unroll
        for (int i = 0; i < 8; i++) selhist[tid + i * 512] = 0;
        __syncthreads();
#pragma unroll 1
        for (int itx = 0; itx < 16; itx++) {
            float4 v = *(const float4*)(srow + itx * 2048 + tid * 4);
            float sv[4] = {v.x, v.y, v.z, v.w};
#pragma unroll
            for (int c = 0; c < 4; c++) {
                u32 k = f2key(sv[c]);
                bool part = (done == 0) || ((k >> (32 - done)) == prefix);
                unsigned d = part ? ((k << done) >> (32 - lb)) : 0xFFFFFFFFu;
                unsigned m = __match_any_sync(0xffffffffu, d);
                if (part && (m & ltm) == 0)
                    atomicAdd(&selhist[d], __popc(m));
            }
        }
        __syncthreads();
        // scan 4096 (8 per thread, 16 warps)
        u32 h8[8], ex8[8];
#pragma unroll
        for (int i = 0; i < 8; i++) h8[i] = selhist[tid * 8 + i];
        u32 s = 0;
#pragma unroll
        for (int i = 0; i < 8; i++) s += h8[i];
        u32 inc = s;
#pragma unroll
        for (int o = 1; o < 32; o <<= 1) {
            u32 n = __shfl_up_sync(0xffffffffu, inc, o);
            if (lane >= o) inc += n;
        }
        if (lane == 31) red[w] = inc;
        __syncthreads();
        if (tid < 32) {
            u32 v2 = (tid < 16) ? red[tid] : 0u;
#pragma unroll
            for (int o = 1; o < 32; o <<= 1) {
                u32 n = __shfl_up_sync(0xffffffffu, v2, o);
                if (tid >= o) v2 += n;
            }
            if (tid < 16) red[32 + tid] = v2;
        }
        __syncthreads();
        u32 wb = (w == 0) ? 0u : red[32 + w - 1];
        u32 run = wb + inc - s;
#pragma unroll
        for (int i = 0; i < 8; i++) { ex8[i] = run; run += h8[i]; }
        u32 T = red[32 + 15];
#pragma unroll
        for (int i = 0; i < 8; i++) {
            u32 cg = T - ex8[i] - h8[i];
            if (h8[i] && base_gt + cg < MAXP && base_gt + cg + h8[i] >= MAXP) {
                red[64] = (u32)(tid * 8 + i);
                red[65] = cg;
            }
        }
        __syncthreads();
        prefix = (prefix << lb) | red[64];
        base_gt += red[65];
        __syncthreads();
    }
    const unsigned V = prefix;

    // ---- stable compaction: >V then ==V (ascending idx) into keyA/idxA -----
    const int beg = tid * 64;
    int cgt = 0, ceq = 0;
#pragma unroll 4
    for (int q = 0; q < 16; q++) {
        float4 v = *(const float4*)(srow + beg + q * 4);
        float sv[4] = {v.x, v.y, v.z, v.w};
#pragma unroll
        for (int c = 0; c < 4; c++) {
            u32 k = f2key(sv[c]);
            cgt += (k > V); ceq += (k == V);
        }
    }
    int vg = cgt, ve = ceq;
#pragma unroll
    for (int o = 1; o < 32; o <<= 1) {
        int ng = __shfl_up_sync(0xffffffffu, vg, o);
        int ne = __shfl_up_sync(0xffffffffu, ve, o);
        if (lane >= o) { vg += ng; ve += ne; }
    }
    if (lane == 31) { red[w] = (u32)vg; red[16 + w] = (u32)ve; }
    __syncthreads();
    if (tid < 32) {
        int wg = (tid < 16) ? (int)red[tid] : 0;
        int we = (tid < 16) ? (int)red[16 + tid] : 0;
#pragma unroll
        for (int o = 1; o < 32; o <<= 1) {
            int ng = __shfl_up_sync(0xffffffffu, wg, o);
            int ne = __shfl_up_sync(0xffffffffu, we, o);
            if (tid >= o) { wg += ng; we += ne; }
        }
        if (tid < 16) { red[32 + tid] = (u32)wg; red[48 + tid] = (u32)we; }
    }
    __syncthreads();
    int bgt = vg - cgt + (w ? (int)red[32 + w - 1] : 0);
    int beq = ve - ceq + (w ? (int)red[48 + w - 1] : 0);
    const int count_gt = (int)red[32 + 15];
    const int need_eq  = MAXP - count_gt;

#pragma unroll 4
    for (int q = 0; q < 16; q++) {
        float4 v = *(const float4*)(srow + beg + q * 4);
        float sv[4] = {v.x, v.y, v.z, v.w};
#pragma unroll
        for (int c = 0; c < 4; c++) {
            u32 k = f2key(sv[c]);
            int j = beg + q * 4 + c;
            if (k > V) {
                keyA[bgt] = ~k; idxA[bgt] = (u16)j; bgt++;
            } else if (k == V) {
                int r = beq++;
                if (r < need_eq) {
                    keyA[count_gt + r] = ~V; idxA[count_gt + r] = (u16)j;
                }
            }
        }
    }
    __syncthreads();

    // ---- stable LSD radix sort: 8 x 4-bit on inverted key (asc ~key) -------
    u32* ks = keyA; u32* kd = keyB;
    u16* is = idxA; u16* id_ = idxB;
#pragma unroll 1
    for (int p = 0; p < 8; p++) {
        const int shift = 4 * p;
#pragma unroll
        for (int i = 0; i < 4; i++) shist[tid + i * 512] = 0;
        __syncthreads();
        u32 kk0[8], kk1[8];
#pragma unroll
        for (int e = 0; e < 8; e++) {
            u32 k0 = ks[e * 1024 + tid * 2];
            u32 k1 = ks[e * 1024 + tid * 2 + 1];
            kk0[e] = k0; kk1[e] = k1;
            u32 d0 = (k0 >> shift) & 15u, d1 = (k1 >> shift) & 15u;
            u32 b0 = __ballot_sync(0xffffffffu, d0 & 1u);
            u32 b1 = __ballot_sync(0xffffffffu, (d0 >> 1) & 1u);
            u32 b2 = __ballot_sync(0xffffffffu, (d0 >> 2) & 1u);
            u32 b3 = __ballot_sync(0xffffffffu, (d0 >> 3) & 1u);
            u32 c0 = __ballot_sync(0xffffffffu, d1 & 1u);
            u32 c1 = __ballot_sync(0xffffffffu, (d1 >> 1) & 1u);
            u32 c2 = __ballot_sync(0xffffffffu, (d1 >> 2) & 1u);
            u32 c3 = __ballot_sync(0xffffffffu, (d1 >> 3) & 1u);
            if (lane < 16) {
                u32 cnt = (u32)__popc(rec4(b0, b1, b2, b3, lane))
                        + (u32)__popc(rec4(c0, c1, c2, c3, lane));
                shist[lane * 128 + e * 16 + w] = cnt;
            }
        }
        __syncthreads();
        // scan 2048 (4 per thread, 16 warps)
        {
            u32 h4[4];
#pragma unroll
            for (int i = 0; i < 4; i++) h4[i] = shist[tid * 4 + i];
            u32 s = h4[0] + h4[1] + h4[2] + h4[3];
            u32 inc = s;
#pragma unroll
            for (int o = 1; o < 32; o <<= 1) {
                u32 n = __shfl_up_sync(0xffffffffu, inc, o);
                if (lane >= o) inc += n;
            }
            if (lane == 31) red[w] = inc;
            __syncthreads();
            if (tid < 32) {
                u32 v2 = (tid < 16) ? red[tid] : 0u;
#pragma unroll
                for (int o = 1; o < 32; o <<= 1) {
                    u32 n = __shfl_up_sync(0xffffffffu, v2, o);
                    if (tid >= o) v2 += n;
                }
                if (tid < 16) red[32 + tid] = v2;
            }
            __syncthreads();
            u32 wb = (w == 0) ? 0u : red[32 + w - 1];
            u32 run = wb + inc - s;
#pragma unroll
            for (int i = 0; i < 4; i++) { shist[tid * 4 + i] = run; run += h4[i]; }
        }
        __syncthreads();
#pragma unroll
        for (int e = 0; e < 8; e++) {
            u32 k0 = kk0[e], k1 = kk1[e];
            u32 d0 = (k0 >> shift) & 15u, d1 = (k1 >> shift) & 15u;
            u32 b0 = __ballot_sync(0xffffffffu, d0 & 1u);
            u32 b1 = __ballot_sync(0xffffffffu, (d0 >> 1) & 1u);
            u32 b2 = __ballot_sync(0xffffffffu, (d0 >> 2) & 1u);
            u32 b3 = __ballot_sync(0xffffffffu, (d0 >> 3) & 1u);
            u32 c0 = __ballot_sync(0xffffffffu, d1 & 1u);
            u32 c1 = __ballot_sync(0xffffffffu, (d1 >> 1) & 1u);
            u32 c2 = __ballot_sync(0xffffffffu, (d1 >> 2) & 1u);
            u32 c3 = __ballot_sync(0xffffffffu, (d1 >> 3) & 1u);
            // position order within segment: (lane, sub) ascending
            u32 r0 = (u32)__popc(rec4(b0,b1,b2,b3,d0) & ltm)
                   + (u32)__popc(rec4(c0,c1,c2,c3,d0) & ltm);
            u32 r1 = (u32)__popc(rec4(b0,b1,b2,b3,d1) & ltm)
                   + (u32)__popc(rec4(c0,c1,c2,c3,d1) & ltm)
                   + (d0 == d1 ? 1u : 0u);
            u32 p0 = shist[d0 * 128 + e * 16 + w] + r0;
            u32 p1 = shist[d1 * 128 + e * 16 + w] + r1;
            kd[p0] = k0; id_[p0] = is[e * 1024 + tid * 2];
            kd[p1] = k1; id_[p1] = is[e * 1024 + tid * 2 + 1];
        }
        __syncthreads();
        u32* tk = ks; ks = kd; kd = tk;
        u16* ti = is; is = id_; id_ = ti;
    }
    // 8 passes -> sorted result back in keyA/idxA (== ks/is)

    // ---- softmax over first `budget` entries --------------------------------
    const float s0 = key2f(~ks[0]);
    const int budget = g_budget;
    float part = 0.0f;
    float ev[16]; u16 iv[16];
#pragma unroll
    for (int i = 0; i < 16; i++) {
        int pp = tid + i * 512;
        u32 kk = ks[pp];
        iv[i] = is[pp];
        float e = (pp < budget) ? expf(key2f(~kk) - s0) : 0.0f;
        ev[i] = e;
        part += e;
    }
#pragma unroll
    for (int o = 16; o > 0; o >>= 1) part += __shfl_down_sync(0xffffffffu, part, o);
    __syncthreads();
    if (lane == 0) fred[66 + w] = part;
    __syncthreads();
    if (tid == 0) {
        float s = 0.0f;
        for (int ww = 0; ww < 16; ww++) s += fred[66 + ww];
        fred[82] = s;
    }
    __syncthreads();
    const float denom = fred[82];

#pragma unroll
    for (int i = 0; i < 16; i++) {
        int pp = tid + i * 512;
        out_idx[(size_t)row * MAXP + pp] = (float)iv[i];
        out_w  [(size_t)row * MAXP + pp] = ev[i] / denom;
    }
}

// ---------------- launch -----------------------------------------------------
extern "C" void kernel_launch(void* const* d_in, const int* in_sizes, int n_in,
                              void* d_out, int out_size)
{
    const float* x    = (const float*)d_in[0];
    const float* noise= (const float*)d_in[1];
    const float* W1c  = (const float*)d_in[2];
    const float* b1c  = (const float*)d_in[3];
    const float* W2c  = (const float*)d_in[4];
    const float* b2c  = (const float*)d_in[5];
    const float* Ws1  = (const float*)d_in[6];
    const float* bs1  = (const float*)d_in[7];
    const float* Ws2  = (const float*)d_in[8];
    const float* bs2  = (const float*)d_in[9];

    float* out        = (float*)d_out;
    float* out_idx    = out;
    float* out_budget = out + (size_t)BATCH * MAXP;
    float* out_w      = out_budget + 1;
    float* out_comp   = out_w + (size_t)BATCH * MAXP;

    float *hTp, *sp;
    cudaGetSymbolAddress((void**)&hTp, g_hT);
    cudaGetSymbolAddress((void**)&sp,  g_scores);

    sgemm_fused<<<dim3(9, 16), 256>>>(x, Ws1, bs1, W1c, b1c);
    comp_kernel<<<256, 256>>>(W2c, b2c, out_comp);
    budget_kernel<<<1, 1024>>>(out_budget);

    sgemm_scores_ca<<<dim3(256, 16), 256>>>(hTp, Ws2, bs2, noise, sp);

    cudaFuncSetAttribute(topk_kernel, cudaFuncAttributeMaxDynamicSharedMemorySize, TOPK_SMEM);
    topk_kernel<<<BATCH, 512, TOPK_SMEM>>>(out_idx, out_w);
}

// round 9
// speedup vs baseline: 1.2678x; 1.0524x over previous
#include <cuda_runtime.h>
#include <math.h>
#include <stdint.h>

#define BATCH    2048
#define IN_DIM   2048
#define POOLN    32768
#define HIDN     1024
#define MAXP     8192
#define MINP     512

typedef unsigned long long u64;
typedef unsigned int u32;
typedef unsigned short u16;

// ---------------- scratch (device globals: no allocations allowed) ----------
__device__ float g_c1[BATCH * 128];
__device__ float g_hT[(size_t)HIDN * BATCH];        // h transposed: [k][row]
__device__ float g_scores[(size_t)BATCH * POOLN];   // 256 MB
__device__ float g_comp[BATCH];
__device__ int   g_budget;

// ---------------- cp.async helpers ------------------------------------------
__device__ __forceinline__ void cpa16(void* smem, const void* gmem) {
    unsigned s = (unsigned)__cvta_generic_to_shared(smem);
    asm volatile("cp.async.cg.shared.global [%0], [%1], 16;" :: "r"(s), "l"(gmem));
}
#define CP_COMMIT()  asm volatile("cp.async.commit_group;")
#define CP_WAIT(n)   asm volatile("cp.async.wait_group %0;" :: "n"(n))

// ============================================================================
// fused x-GEMM core (unchanged from R7/R8)
// ============================================================================
#define GEMM_STS(buf)                                                            \
    As[buf][ca0*4+0][r_a]=ra0.x; As[buf][ca0*4+1][r_a]=ra0.y;                    \
    As[buf][ca0*4+2][r_a]=ra0.z; As[buf][ca0*4+3][r_a]=ra0.w;                    \
    As[buf][ca0*4+4][r_a]=ra1.x; As[buf][ca0*4+5][r_a]=ra1.y;                    \
    As[buf][ca0*4+6][r_a]=ra1.z; As[buf][ca0*4+7][r_a]=ra1.w;                    \
    *(float4*)&Bs[buf][r_b][cb0*4]     = rb0;                                    \
    *(float4*)&Bs[buf][r_b][cb0*4 + 4] = rb1;

#define GEMM_LDG(k0)                                                             \
    {   const float* Ap = Abase + (k0);                                          \
        ra0 = *(const float4*)(Ap + ca0*4);                                      \
        ra1 = *(const float4*)(Ap + ca0*4 + 4);                                  \
        const float* Bp = (Bb) + (size_t)((k0) + r_b) * Nstride;                 \
        rb0 = *(const float4*)(Bp + cb0*4);                                      \
        rb1 = *(const float4*)(Bp + cb0*4 + 4);                                  \
    }

#define GEMM_PIPE(Ab, Bb, KDIM)                                                  \
    float acc[8][8];                                                             \
    _Pragma("unroll")                                                            \
    for (int i = 0; i < 8; i++)                                                  \
        _Pragma("unroll")                                                        \
        for (int j = 0; j < 8; j++) acc[i][j] = 0.0f;                            \
    const int r_a = tid >> 1, ca0 = (tid & 1) * 2;                               \
    const int r_b = tid >> 4, cb0 = (tid & 15) * 2;                              \
    const float* Abase = (Ab) + (size_t)r_a * (KDIM);                            \
    float4 ra0, ra1, rb0, rb1;                                                   \
    GEMM_LDG(0)                                                                  \
    GEMM_STS(0)                                                                  \
    __syncthreads();                                                             \
    const int ITERS = (KDIM) / 16;                                               \
    for (int it = 0; it < ITERS; it++) {                                         \
        const int cur = it & 1;                                                  \
        if (it + 1 < ITERS) { GEMM_LDG((it + 1) * 16) }                          \
        _Pragma("unroll")                                                        \
        for (int k = 0; k < 16; k++) {                                           \
            float a[8], b[8];                                                    \
            const float4* a4 = (const float4*)&As[cur][k][tm * 8];               \
            const float4* b4 = (const float4*)&Bs[cur][k][tn * 8];               \
            float4 av0 = a4[0], av1 = a4[1];                                     \
            float4 bv0 = b4[0], bv1 = b4[1];                                     \
            a[0]=av0.x; a[1]=av0.y; a[2]=av0.z; a[3]=av0.w;                      \
            a[4]=av1.x; a[5]=av1.y; a[6]=av1.z; a[7]=av1.w;                      \
            b[0]=bv0.x; b[1]=bv0.y; b[2]=bv0.z; b[3]=bv0.w;                      \
            b[4]=bv1.x; b[5]=bv1.y; b[6]=bv1.z; b[7]=bv1.w;                      \
            _Pragma("unroll")                                                    \
            for (int i = 0; i < 8; i++)                                          \
                _Pragma("unroll")                                                \
                for (int j = 0; j < 8; j++) acc[i][j] += a[i] * b[j];            \
        }                                                                        \
        if (it + 1 < ITERS) { GEMM_STS(cur ^ 1) }                                \
        __syncthreads();                                                         \
    }

__global__ void __launch_bounds__(256, 2) sgemm_fused(
    const float* __restrict__ x,
    const float* __restrict__ Ws1, const float* __restrict__ bs1,
    const float* __restrict__ W1c, const float* __restrict__ b1c)
{
    __shared__ float As[2][16][128];
    __shared__ float Bs[2][16][128];
    const int bx = blockIdx.x, by = blockIdx.y;
    const int tid = threadIdx.x;
    const int tn = tid & 15, tm = tid >> 4;

    const bool is_c1 = (bx == 8);
    const float* Bsel = is_c1 ? W1c : Ws1;
    const float* bias = is_c1 ? b1c : bs1;
    const int Nstride = is_c1 ? 128 : HIDN;
    const int cb      = is_c1 ? 0 : bx * 128;

    const float* Ab = x + (size_t)by * 128 * IN_DIM;
    const float* Bb = Bsel + cb;

    GEMM_PIPE(Ab, Bb, IN_DIM)

    const float4 bi0 = *(const float4*)&bias[tn * 8];
    const float4 bi1 = *(const float4*)&bias[tn * 8 + 4];
    float r_[8][8];
#pragma unroll
    for (int i = 0; i < 8; i++) {
        r_[i][0] = fmaxf(__fadd_rn(acc[i][0], bi0.x), 0.0f);
        r_[i][1] = fmaxf(__fadd_rn(acc[i][1], bi0.y), 0.0f);
        r_[i][2] = fmaxf(__fadd_rn(acc[i][2], bi0.z), 0.0f);
        r_[i][3] = fmaxf(__fadd_rn(acc[i][3], bi0.w), 0.0f);
        r_[i][4] = fmaxf(__fadd_rn(acc[i][4], bi1.x), 0.0f);
        r_[i][5] = fmaxf(__fadd_rn(acc[i][5], bi1.y), 0.0f);
        r_[i][6] = fmaxf(__fadd_rn(acc[i][6], bi1.z), 0.0f);
        r_[i][7] = fmaxf(__fadd_rn(acc[i][7], bi1.w), 0.0f);
    }
    const int row0 = by * 128 + tm * 8;
    if (!is_c1) {
#pragma unroll
        for (int j = 0; j < 8; j++) {
            const int col = cb + tn * 8 + j;
            float4 lo = make_float4(r_[0][j], r_[1][j], r_[2][j], r_[3][j]);
            float4 hi = make_float4(r_[4][j], r_[5][j], r_[6][j], r_[7][j]);
            float* cp = g_hT + (size_t)col * BATCH + row0;
            *(float4*)cp = lo;
            *(float4*)(cp + 4) = hi;
        }
    } else {
#pragma unroll
        for (int i = 0; i < 8; i++) {
            float* cp = g_c1 + (size_t)(row0 + i) * 128 + tn * 8;
            *(float4*)cp = make_float4(r_[i][0], r_[i][1], r_[i][2], r_[i][3]);
            *(float4*)(cp + 4) = make_float4(r_[i][4], r_[i][5], r_[i][6], r_[i][7]);
        }
    }
}

// ============================================================================
// scores GEMM: 256x128 CTA tile, 16x8 per-thread tile, cp.async 3-stage ring.
// A = hT [HIDN][BATCH] (k-major), B = Ws2 [HIDN][POOLN] (k-major).
// Thread (tm,tn): rows tm*16..+15, cols {tn*4..+3} and {64+tn*4..+3}.
// acc[i][j] accumulates strictly ascending k -> scores bitwise identical.
// ============================================================================
#define AS_(buf,k,c) Asm[((buf)*16 + (k))*256 + (c)]
#define BS_(buf,k,c) Bsm[((buf)*16 + (k))*128 + (c)]

#define FRAG_LD3(av, bv, buf, k)                                                 \
    {   const float4* a4 = (const float4*)&AS_(buf, k, tm * 16);                 \
        float4 t0 = a4[0], t1 = a4[1], t2 = a4[2], t3 = a4[3];                   \
        float4 u0 = *(const float4*)&BS_(buf, k, tn * 4);                        \
        float4 u1 = *(const float4*)&BS_(buf, k, 64 + tn * 4);                   \
        av[0]=t0.x;  av[1]=t0.y;  av[2]=t0.z;  av[3]=t0.w;                       \
        av[4]=t1.x;  av[5]=t1.y;  av[6]=t1.z;  av[7]=t1.w;                       \
        av[8]=t2.x;  av[9]=t2.y;  av[10]=t2.z; av[11]=t2.w;                      \
        av[12]=t3.x; av[13]=t3.y; av[14]=t3.z; av[15]=t3.w;                      \
        bv[0]=u0.x; bv[1]=u0.y; bv[2]=u0.z; bv[3]=u0.w;                          \
        bv[4]=u1.x; bv[5]=u1.y; bv[6]=u1.z; bv[7]=u1.w;                          \
    }

#define FMA_BLOCK16(av, bv)                                                      \
    _Pragma("unroll")                                                            \
    for (int i = 0; i < 16; i++)                                                 \
        _Pragma("unroll")                                                        \
        for (int j = 0; j < 8; j++) acc[i][j] += av[i] * bv[j];

#define SC_SMEM (3 * 16 * 256 * 4 + 3 * 16 * 128 * 4)   // 73728 B

__global__ void __launch_bounds__(256, 1) sgemm_scores_ca(
    const float* __restrict__ AT, const float* __restrict__ B,
    const float* __restrict__ bias, const float* __restrict__ noise,
    float* __restrict__ C)
{
    extern __shared__ float smem_f[];
    float* Asm = smem_f;                     // 3 stages x 16 x 256
    float* Bsm = smem_f + 3 * 16 * 256;      // 3 stages x 16 x 128
    const int bx = blockIdx.x, by = blockIdx.y;
    const int tid = threadIdx.x;
    const int tn = tid & 15, tm = tid >> 4;

    // copy mapping: A 4 float4/thread, B 2 float4/thread per stage
    const int fa0 = tid, fa1 = tid + 256, fa2 = tid + 512, fa3 = tid + 768;
    const int ra0_ = fa0 >> 6, ca0_ = (fa0 & 63) * 4;
    const int ra1_ = fa1 >> 6, ca1_ = (fa1 & 63) * 4;
    const int ra2_ = fa2 >> 6, ca2_ = (fa2 & 63) * 4;
    const int ra3_ = fa3 >> 6, ca3_ = (fa3 & 63) * 4;
    const int fb0 = tid, fb1 = tid + 256;
    const int rb0_ = fb0 >> 5, cb0_ = (fb0 & 31) * 4;
    const int rb1_ = fb1 >> 5, cb1_ = (fb1 & 31) * 4;

    const float* gA0 = AT + (size_t)ra0_ * BATCH + by * 256 + ca0_;
    const float* gA1 = AT + (size_t)ra1_ * BATCH + by * 256 + ca1_;
    const float* gA2 = AT + (size_t)ra2_ * BATCH + by * 256 + ca2_;
    const float* gA3 = AT + (size_t)ra3_ * BATCH + by * 256 + ca3_;
    const float* gB0 = B  + (size_t)rb0_ * POOLN + bx * 128 + cb0_;
    const float* gB1 = B  + (size_t)rb1_ * POOLN + bx * 128 + cb1_;
    const size_t stepA = (size_t)16 * BATCH;
    const size_t stepB = (size_t)16 * POOLN;

#define CPA_TILE3(buf)                                                           \
    {   cpa16(&AS_(buf, ra0_, ca0_), gA0);                                       \
        cpa16(&AS_(buf, ra1_, ca1_), gA1);                                       \
        cpa16(&AS_(buf, ra2_, ca2_), gA2);                                       \
        cpa16(&AS_(buf, ra3_, ca3_), gA3);                                       \
        cpa16(&BS_(buf, rb0_, cb0_), gB0);                                       \
        cpa16(&BS_(buf, rb1_, cb1_), gB1);                                       \
        CP_COMMIT();                                                             \
        gA0 += stepA; gA1 += stepA; gA2 += stepA; gA3 += stepA;                  \
        gB0 += stepB; gB1 += stepB; }

    float acc[16][8];
#pragma unroll
    for (int i = 0; i < 16; i++)
#pragma unroll
        for (int j = 0; j < 8; j++) acc[i][j] = 0.0f;

    CPA_TILE3(0)
    CPA_TILE3(1)

    float af0[16], af1[16], bf0[8], bf1[8];
    const int ITERS = HIDN / 16;   // 64
    for (int it = 0; it < ITERS; it++) {
        const int cur = it % 3;
        CP_WAIT(1);
        __syncthreads();
        FRAG_LD3(af0, bf0, cur, 0)
#pragma unroll
        for (int k = 0; k < 15; k++) {
            if (k & 1) { FRAG_LD3(af0, bf0, cur, k + 1) FMA_BLOCK16(af1, bf1) }
            else       { FRAG_LD3(af1, bf1, cur, k + 1) FMA_BLOCK16(af0, bf0) }
        }
        if (it + 2 < ITERS) { CPA_TILE3((it + 2) % 3) }
        else                { CP_COMMIT(); }
        FMA_BLOCK16(af1, bf1)
    }

    const int colL = bx * 128 + tn * 4;
    const int colH = colL + 64;
    const float4 biL = *(const float4*)&bias[colL];
    const float4 biH = *(const float4*)&bias[colH];
#pragma unroll
    for (int i = 0; i < 16; i++) {
        const int row = by * 256 + tm * 16 + i;
        const float* np = noise + (size_t)row * POOLN;
        float4 nL = *(const float4*)(np + colL);
        float4 nH = *(const float4*)(np + colH);
        float4 oL, oH;
        oL.x = __fadd_rn(__fadd_rn(acc[i][0], biL.x), __fmul_rn(nL.x, 0.1f));
        oL.y = __fadd_rn(__fadd_rn(acc[i][1], biL.y), __fmul_rn(nL.y, 0.1f));
        oL.z = __fadd_rn(__fadd_rn(acc[i][2], biL.z), __fmul_rn(nL.z, 0.1f));
        oL.w = __fadd_rn(__fadd_rn(acc[i][3], biL.w), __fmul_rn(nL.w, 0.1f));
        oH.x = __fadd_rn(__fadd_rn(acc[i][4], biH.x), __fmul_rn(nH.x, 0.1f));
        oH.y = __fadd_rn(__fadd_rn(acc[i][5], biH.y), __fmul_rn(nH.y, 0.1f));
        oH.z = __fadd_rn(__fadd_rn(acc[i][6], biH.z), __fmul_rn(nH.z, 0.1f));
        oH.w = __fadd_rn(__fadd_rn(acc[i][7], biH.w), __fmul_rn(nH.w, 0.1f));
        float* cp = C + (size_t)row * POOLN;
        *(float4*)(cp + colL) = oL;
        *(float4*)(cp + colH) = oH;
    }
}

// ---------------- comp stage 2 / budget (unchanged) --------------------------
__global__ void comp_kernel(const float* __restrict__ W2c,
                            const float* __restrict__ b2c,
                            float* __restrict__ out_comp)
{
    int row  = blockIdx.x * 8 + (threadIdx.x >> 5);
    int lane = threadIdx.x & 31;
    float p = 0.0f;
#pragma unroll
    for (int t = lane; t < 128; t += 32) p += g_c1[row * 128 + t] * W2c[t];
#pragma unroll
    for (int o = 16; o > 0; o >>= 1) p += __shfl_down_sync(0xffffffffu, p, o);
    if (lane == 0) {
        float z = p + b2c[0];
        float c = 1.0f / (1.0f + expf(-z));
        g_comp[row]  = c;
        out_comp[row] = c;
    }
}

__global__ void budget_kernel(float* __restrict__ out_budget)
{
    __shared__ float ws[32];
    int tid = threadIdx.x;
    float s = g_comp[tid] + g_comp[tid + 1024];
#pragma unroll
    for (int o = 16; o > 0; o >>= 1) s += __shfl_down_sync(0xffffffffu, s, o);
    if ((tid & 31) == 0) ws[tid >> 5] = s;
    __syncthreads();
    if (tid < 32) {
        float v = ws[tid];
#pragma unroll
        for (int o = 16; o > 0; o >>= 1) v += __shfl_down_sync(0xffffffffu, v, o);
        if (tid == 0) {
            float mean  = v / 2048.0f;
            float scale = mean * mean;
            float t = 512.0f + 7680.0f * scale;
            int b = (int)floorf(t);
            if (b < MINP) b = MINP;
            if (b > MAXP) b = MAXP;
            g_budget = b;
            out_budget[0] = (float)b;
        }
    }
}

// ============================================================================
// top-k + softmax (unchanged from R8)
// ============================================================================
__device__ __forceinline__ unsigned f2key(float s) {
    unsigned b = __float_as_uint(s);
    return (b & 0x80000000u) ? ~b : (b | 0x80000000u);
}
__device__ __forceinline__ float key2f(unsigned k) {
    return __uint_as_float((k & 0x80000000u) ? (k ^ 0x80000000u) : ~k);
}
__device__ __forceinline__ u32 rec4(u32 b0, u32 b1, u32 b2, u32 b3, u32 d) {
    u32 m = (d & 1u) ? b0 : ~b0;
    m &= (d & 2u) ? b1 : ~b1;
    m &= (d & 4u) ? b2 : ~b2;
    m &= (d & 8u) ? b3 : ~b3;
    return m;
}

#define OFF_KEYA   0
#define OFF_KEYB   32768
#define OFF_IDXA   65536
#define OFF_IDXB   81920
#define OFF_SHIST  98304
#define OFF_RED    106496
#define TOPK_SMEM  (106496 + 384)

__global__ void __launch_bounds__(512, 2) topk_kernel(
    float* __restrict__ out_idx, float* __restrict__ out_w)
{
    extern __shared__ unsigned char smem_raw[];
    u32* keyA    = (u32*)(smem_raw + OFF_KEYA);
    u32* keyB    = (u32*)(smem_raw + OFF_KEYB);
    u16* idxA    = (u16*)(smem_raw + OFF_IDXA);
    u16* idxB    = (u16*)(smem_raw + OFF_IDXB);
    u32* shist   = (u32*)(smem_raw + OFF_SHIST);
    u32* selhist = (u32*)(smem_raw + OFF_KEYB);
    u32* red     = (u32*)(smem_raw + OFF_RED);
    float* fred  = (float*)red;

    const int row = blockIdx.x;
    const int tid = threadIdx.x;
    const int w   = tid >> 5, lane = tid & 31;
    const unsigned ltm = (1u << lane) - 1u;
    const float* srow = g_scores + (size_t)row * POOLN;

    unsigned prefix = 0;
    u32 base_gt = 0;
#pragma unroll 1
    for (int lvl = 0; lvl < 3; lvl++) {
        const int lb   = (lvl < 2) ? 12 : 8;
        const int done = (lvl == 0) ? 0 : (lvl == 1 ? 12 : 24);
#pragma unroll
        for (int i = 0; i < 8; i++) selhist[tid + i * 512] = 0;
        __syncthreads();
#pragma unroll 1
        for (int itx = 0; itx < 16; itx++) {
            float4 v = *(const float4*)(srow + itx * 2048 + tid * 4);
            float sv[4] = {v.x, v.y, v.z, v.w};
#pragma unroll
            for (int c = 0; c < 4; c++) {
                u32 k = f2key(sv[c]);
                bool part = (done == 0) || ((k >> (32 - done)) == prefix);
                unsigned d = part ? ((k << done) >> (32 - lb)) : 0xFFFFFFFFu;
                unsigned m = __match_any_sync(0xffffffffu, d);
                if (part && (m & ltm) == 0)
                    atomicAdd(&selhist[d], __popc(m));
            }
        }
        __syncthreads();
        u32 h8[8], ex8[8];
#pragma unroll
        for (int i = 0; i < 8; i++) h8[i] = selhist[tid * 8 + i];
        u32 s = 0;
#pragma unroll
        for (int i = 0; i < 8; i++) s += h8[i];
        u32 inc = s;
#pragma unroll
        for (int o = 1; o < 32; o <<= 1) {
            u32 n = __shfl_up_sync(0xffffffffu, inc, o);
            if (lane >= o) inc += n;
        }
        if (lane == 31) red[w] = inc;
        __syncthreads();
        if (tid < 32) {
            u32 v2 = (tid < 16) ? red[tid] : 0u;
#pragma unroll
            for (int o = 1; o < 32; o <<= 1) {
                u32 n = __shfl_up_sync(0xffffffffu, v2, o);
                if (tid >= o) v2 += n;
            }
            if (tid < 16) red[32 + tid] = v2;
        }
        __syncthreads();
        u32 wb = (w == 0) ? 0u : red[32 + w - 1];
        u32 run = wb + inc - s;
#pragma unroll
        for (int i = 0; i < 8; i++) { ex8[i] = run; run += h8[i]; }
        u32 T = red[32 + 15];
#pragma unroll
        for (int i = 0; i < 8; i++) {
            u32 cg = T - ex8[i] - h8[i];
            if (h8[i] && base_gt + cg < MAXP && base_gt + cg + h8[i] >= MAXP) {
                red[64] = (u32)(tid * 8 + i);
                red[65] = cg;
            }
        }
        __syncthreads();
        prefix = (prefix << lb) | red[64];
        base_gt += red[65];
        __syncthreads();
    }
    const unsigned V = prefix;

    const int beg = tid * 64;
    int cgt = 0, ceq = 0;
#pragma unroll 4
    for (int q = 0; q < 16; q++) {
        float4 v = *(const float4*)(srow + beg + q * 4);
        float sv[4] = {v.x, v.y, v.z, v.w};
#pragma unroll
        for (int c = 0; c < 4; c++) {
            u32 k = f2key(sv[c]);
            cgt += (k > V); ceq += (k == V);
        }
    }
    int vg = cgt, ve = ceq;
#pragma unroll
    for (int o = 1; o < 32; o <<= 1) {
        int ng = __shfl_up_sync(0xffffffffu, vg, o);
        int ne = __shfl_up_sync(0xffffffffu, ve, o);
        if (lane >= o) { vg += ng; ve += ne; }
    }
    if (lane == 31) { red[w] = (u32)vg; red[16 + w] = (u32)ve; }
    __syncthreads();
    if (tid < 32) {
        int wg = (tid < 16) ? (int)red[tid] : 0;
        int we = (tid < 16) ? (int)red[16 + tid] : 0;
#pragma unroll
        for (int o = 1; o < 32; o <<= 1) {
            int ng = __shfl_up_sync(0xffffffffu, wg, o);
            int ne = __shfl_up_sync(0xffffffffu, we, o);
            if (tid >= o) { wg += ng; we += ne; }
        }
        if (tid < 16) { red[32 + tid] = (u32)wg; red[48 + tid] = (u32)we; }
    }
    __syncthreads();
    int bgt = vg - cgt + (w ? (int)red[32 + w - 1] : 0);
    int beq = ve - ceq + (w ? (int)red[48 + w - 1] : 0);
    const int count_gt = (int)red[32 + 15];
    const int need_eq  = MAXP - count_gt;

#pragma unroll 4
    for (int q = 0; q < 16; q++) {
        float4 v = *(const float4*)(srow + beg + q * 4);
        float sv[4] = {v.x, v.y, v.z, v.w};
#pragma unroll
        for (int c = 0; c < 4; c++) {
            u32 k = f2key(sv[c]);
            int j = beg + q * 4 + c;
            if (k > V) {
                keyA[bgt] = ~k; idxA[bgt] = (u16)j; bgt++;
            } else if (k == V) {
                int r = beq++;
                if (r < need_eq) {
                    keyA[count_gt + r] = ~V; idxA[count_gt + r] = (u16)j;
                }
            }
        }
    }
    __syncthreads();

    u32* ks = keyA; u32* kd = keyB;
    u16* is = idxA; u16* id_ = idxB;
#pragma unroll 1
    for (int p = 0; p < 8; p++) {
        const int shift = 4 * p;
#pragma unroll
        for (int i = 0; i < 4; i++) shist[tid + i * 512] = 0;
        __syncthreads();
        u32 kk0[8], kk1[8];
#pragma unroll
        for (int e = 0; e < 8; e++) {
            u32 k0 = ks[e * 1024 + tid * 2];
            u32 k1 = ks[e * 1024 + tid * 2 + 1];
            kk0[e] = k0; kk1[e] = k1;
            u32 d0 = (k0 >> shift) & 15u, d1 = (k1 >> shift) & 15u;
            u32 b0 = __ballot_sync(0xffffffffu, d0 & 1u);
            u32 b1 = __ballot_sync(0xffffffffu, (d0 >> 1) & 1u);
            u32 b2 = __ballot_sync(0xffffffffu, (d0 >> 2) & 1u);
            u32 b3 = __ballot_sync(0xffffffffu, (d0 >> 3) & 1u);
            u32 c0 = __ballot_sync(0xffffffffu, d1 & 1u);
            u32 c1 = __ballot_sync(0xffffffffu, (d1 >> 1) & 1u);
            u32 c2 = __ballot_sync(0xffffffffu, (d1 >> 2) & 1u);
            u32 c3 = __ballot_sync(0xffffffffu, (d1 >> 3) & 1u);
            if (lane < 16) {
                u32 cnt = (u32)__popc(rec4(b0, b1, b2, b3, lane))
                        + (u32)__popc(rec4(c0, c1, c2, c3, lane));
                shist[lane * 128 + e * 16 + w] = cnt;
            }
        }
        __syncthreads();
        {
            u32 h4[4];
#pragma unroll
            for (int i = 0; i < 4; i++) h4[i] = shist[tid * 4 + i];
            u32 s = h4[0] + h4[1] + h4[2] + h4[3];
            u32 inc = s;
#pragma unroll
            for (int o = 1; o < 32; o <<= 1) {
                u32 n = __shfl_up_sync(0xffffffffu, inc, o);
                if (lane >= o) inc += n;
            }
            if (lane == 31) red[w] = inc;
            __syncthreads();
            if (tid < 32) {
                u32 v2 = (tid < 16) ? red[tid] : 0u;
#pragma unroll
                for (int o = 1; o < 32; o <<= 1) {
                    u32 n = __shfl_up_sync(0xffffffffu, v2, o);
                    if (tid >= o) v2 += n;
                }
                if (tid < 16) red[32 + tid] = v2;
            }
            __syncthreads();
            u32 wb = (w == 0) ? 0u : red[32 + w - 1];
            u32 run = wb + inc - s;
#pragma unroll
            for (int i = 0; i < 4; i++) { shist[tid * 4 + i] = run; run += h4[i]; }
        }
        __syncthreads();
#pragma unroll
        for (int e = 0; e < 8; e++) {
            u32 k0 = kk0[e], k1 = kk1[e];
            u32 d0 = (k0 >> shift) & 15u, d1 = (k1 >> shift) & 15u;
            u32 b0 = __ballot_sync(0xffffffffu, d0 & 1u);
            u32 b1 = __ballot_sync(0xffffffffu, (d0 >> 1) & 1u);
            u32 b2 = __ballot_sync(0xffffffffu, (d0 >> 2) & 1u);
            u32 b3 = __ballot_sync(0xffffffffu, (d0 >> 3) & 1u);
            u32 c0 = __ballot_sync(0xffffffffu, d1 & 1u);
            u32 c1 = __ballot_sync(0xffffffffu, (d1 >> 1) & 1u);
            u32 c2 = __ballot_sync(0xffffffffu, (d1 >> 2) & 1u);
            u32 c3 = __ballot_sync(0xffffffffu, (d1 >> 3) & 1u);
            u32 r0 = (u32)__popc(rec4(b0,b1,b2,b3,d0) & ltm)
                   + (u32)__popc(rec4(c0,c1,c2,c3,d0) & ltm);
            u32 r1 = (u32)__popc(rec4(b0,b1,b2,b3,d1) & ltm)
                   + (u32)__popc(rec4(c0,c1,c2,c3,d1) & ltm)
                   + (d0 == d1 ? 1u : 0u);
            u32 p0 = shist[d0 * 128 + e * 16 + w] + r0;
            u32 p1 = shist[d1 * 128 + e * 16 + w] + r1;
            kd[p0] = k0; id_[p0] = is[e * 1024 + tid * 2];
            kd[p1] = k1; id_[p1] = is[e * 1024 + tid * 2 + 1];
        }
        __syncthreads();
        u32* tk = ks; ks = kd; kd = tk;
        u16* ti = is; is = id_; id_ = ti;
    }

    const float s0 = key2f(~ks[0]);
    const int budget = g_budget;
    float part = 0.0f;
    float ev[16]; u16 iv[16];
#pragma unroll
    for (int i = 0; i < 16; i++) {
        int pp = tid + i * 512;
        u32 kk = ks[pp];
        iv[i] = is[pp];
        float e = (pp < budget) ? expf(key2f(~kk) - s0) : 0.0f;
        ev[i] = e;
        part += e;
    }
#pragma unroll
    for (int o = 16; o > 0; o >>= 1) part += __shfl_down_sync(0xffffffffu, part, o);
    __syncthreads();
    if (lane == 0) fred[66 + w] = part;
    __syncthreads();
    if (tid == 0) {
        float s = 0.0f;
        for (int ww = 0; ww < 16; ww++) s += fred[66 + ww];
        fred[82] = s;
    }
    __syncthreads();
    const float denom = fred[82];

#pragma unroll
    for (int i = 0; i < 16; i++) {
        int pp = tid + i * 512;
        out_idx[(size_t)row * MAXP + pp] = (float)iv[i];
        out_w  [(size_t)row * MAXP + pp] = ev[i] / denom;
    }
}

// ---------------- launch -----------------------------------------------------
extern "C" void kernel_launch(void* const* d_in, const int* in_sizes, int n_in,
                              void* d_out, int out_size)
{
    const float* x    = (const float*)d_in[0];
    const float* noise= (const float*)d_in[1];
    const float* W1c  = (const float*)d_in[2];
    const float* b1c  = (const float*)d_in[3];
    const float* W2c  = (const float*)d_in[4];
    const float* b2c  = (const float*)d_in[5];
    const float* Ws1  = (const float*)d_in[6];
    const float* bs1  = (const float*)d_in[7];
    const float* Ws2  = (const float*)d_in[8];
    const float* bs2  = (const float*)d_in[9];

    float* out        = (float*)d_out;
    float* out_idx    = out;
    float* out_budget = out + (size_t)BATCH * MAXP;
    float* out_w      = out_budget + 1;
    float* out_comp   = out_w + (size_t)BATCH * MAXP;

    float *hTp, *sp;
    cudaGetSymbolAddress((void**)&hTp, g_hT);
    cudaGetSymbolAddress((void**)&sp,  g_scores);

    sgemm_fused<<<dim3(9, 16), 256>>>(x, Ws1, bs1, W1c, b1c);
    comp_kernel<<<256, 256>>>(W2c, b2c, out_comp);
    budget_kernel<<<1, 1024>>>(out_budget);

    cudaFuncSetAttribute(sgemm_scores_ca, cudaFuncAttributeMaxDynamicSharedMemorySize, SC_SMEM);
    sgemm_scores_ca<<<dim3(256, 8), 256, SC_SMEM>>>(hTp, Ws2, bs2, noise, sp);

    cudaFuncSetAttribute(topk_kernel, cudaFuncAttributeMaxDynamicSharedMemorySize, TOPK_SMEM);
    topk_kernel<<<BATCH, 512, TOPK_SMEM>>>(out_idx, out_w);
}

// round 10
// speedup vs baseline: 1.3047x; 1.0292x over previous
#include <cuda_runtime.h>
#include <math.h>
#include <stdint.h>

#define BATCH    2048
#define IN_DIM   2048
#define POOLN    32768
#define HIDN     1024
#define MAXP     8192
#define MINP     512

typedef unsigned long long u64;
typedef unsigned int u32;
typedef unsigned short u16;

// ---------------- scratch (device globals: no allocations allowed) ----------
__device__ float g_c1[BATCH * 128];
__device__ float g_hT[(size_t)HIDN * BATCH];        // h transposed: [k][row]
__device__ float g_scores[(size_t)BATCH * POOLN];   // 256 MB
__device__ float g_comp[BATCH];
__device__ int   g_budget;

// ---------------- cp.async helpers ------------------------------------------
__device__ __forceinline__ void cpa16(void* smem, const void* gmem) {
    unsigned s = (unsigned)__cvta_generic_to_shared(smem);
    asm volatile("cp.async.cg.shared.global [%0], [%1], 16;" :: "r"(s), "l"(gmem));
}
#define CP_COMMIT()  asm volatile("cp.async.commit_group;")
#define CP_WAIT(n)   asm volatile("cp.async.wait_group %0;" :: "n"(n))

// ============================================================================
// fused x-GEMM core (unchanged)
// ============================================================================
#define GEMM_STS(buf)                                                            \
    As[buf][ca0*4+0][r_a]=ra0.x; As[buf][ca0*4+1][r_a]=ra0.y;                    \
    As[buf][ca0*4+2][r_a]=ra0.z; As[buf][ca0*4+3][r_a]=ra0.w;                    \
    As[buf][ca0*4+4][r_a]=ra1.x; As[buf][ca0*4+5][r_a]=ra1.y;                    \
    As[buf][ca0*4+6][r_a]=ra1.z; As[buf][ca0*4+7][r_a]=ra1.w;                    \
    *(float4*)&Bs[buf][r_b][cb0*4]     = rb0;                                    \
    *(float4*)&Bs[buf][r_b][cb0*4 + 4] = rb1;

#define GEMM_LDG(k0)                                                             \
    {   const float* Ap = Abase + (k0);                                          \
        ra0 = *(const float4*)(Ap + ca0*4);                                      \
        ra1 = *(const float4*)(Ap + ca0*4 + 4);                                  \
        const float* Bp = (Bb) + (size_t)((k0) + r_b) * Nstride;                 \
        rb0 = *(const float4*)(Bp + cb0*4);                                      \
        rb1 = *(const float4*)(Bp + cb0*4 + 4);                                  \
    }

#define GEMM_PIPE(Ab, Bb, KDIM)                                                  \
    float acc[8][8];                                                             \
    _Pragma("unroll")                                                            \
    for (int i = 0; i < 8; i++)                                                  \
        _Pragma("unroll")                                                        \
        for (int j = 0; j < 8; j++) acc[i][j] = 0.0f;                            \
    const int r_a = tid >> 1, ca0 = (tid & 1) * 2;                               \
    const int r_b = tid >> 4, cb0 = (tid & 15) * 2;                              \
    const float* Abase = (Ab) + (size_t)r_a * (KDIM);                            \
    float4 ra0, ra1, rb0, rb1;                                                   \
    GEMM_LDG(0)                                                                  \
    GEMM_STS(0)                                                                  \
    __syncthreads();                                                             \
    const int ITERS = (KDIM) / 16;                                               \
    for (int it = 0; it < ITERS; it++) {                                         \
        const int cur = it & 1;                                                  \
        if (it + 1 < ITERS) { GEMM_LDG((it + 1) * 16) }                          \
        _Pragma("unroll")                                                        \
        for (int k = 0; k < 16; k++) {                                           \
            float a[8], b[8];                                                    \
            const float4* a4 = (const float4*)&As[cur][k][tm * 8];               \
            const float4* b4 = (const float4*)&Bs[cur][k][tn * 8];               \
            float4 av0 = a4[0], av1 = a4[1];                                     \
            float4 bv0 = b4[0], bv1 = b4[1];                                     \
            a[0]=av0.x; a[1]=av0.y; a[2]=av0.z; a[3]=av0.w;                      \
            a[4]=av1.x; a[5]=av1.y; a[6]=av1.z; a[7]=av1.w;                      \
            b[0]=bv0.x; b[1]=bv0.y; b[2]=bv0.z; b[3]=bv0.w;                      \
            b[4]=bv1.x; b[5]=bv1.y; b[6]=bv1.z; b[7]=bv1.w;                      \
            _Pragma("unroll")                                                    \
            for (int i = 0; i < 8; i++)                                          \
                _Pragma("unroll")                                                \
                for (int j = 0; j < 8; j++) acc[i][j] += a[i] * b[j];            \
        }                                                                        \
        if (it + 1 < ITERS) { GEMM_STS(cur ^ 1) }                                \
        __syncthreads();                                                         \
    }

__global__ void __launch_bounds__(256, 2) sgemm_fused(
    const float* __restrict__ x,
    const float* __restrict__ Ws1, const float* __restrict__ bs1,
    const float* __restrict__ W1c, const float* __restrict__ b1c)
{
    __shared__ float As[2][16][128];
    __shared__ float Bs[2][16][128];
    const int bx = blockIdx.x, by = blockIdx.y;
    const int tid = threadIdx.x;
    const int tn = tid & 15, tm = tid >> 4;

    const bool is_c1 = (bx == 8);
    const float* Bsel = is_c1 ? W1c : Ws1;
    const float* bias = is_c1 ? b1c : bs1;
    const int Nstride = is_c1 ? 128 : HIDN;
    const int cb      = is_c1 ? 0 : bx * 128;

    const float* Ab = x + (size_t)by * 128 * IN_DIM;
    const float* Bb = Bsel + cb;

    GEMM_PIPE(Ab, Bb, IN_DIM)

    const float4 bi0 = *(const float4*)&bias[tn * 8];
    const float4 bi1 = *(const float4*)&bias[tn * 8 + 4];
    float r_[8][8];
#pragma unroll
    for (int i = 0; i < 8; i++) {
        r_[i][0] = fmaxf(__fadd_rn(acc[i][0], bi0.x), 0.0f);
        r_[i][1] = fmaxf(__fadd_rn(acc[i][1], bi0.y), 0.0f);
        r_[i][2] = fmaxf(__fadd_rn(acc[i][2], bi0.z), 0.0f);
        r_[i][3] = fmaxf(__fadd_rn(acc[i][3], bi0.w), 0.0f);
        r_[i][4] = fmaxf(__fadd_rn(acc[i][4], bi1.x), 0.0f);
        r_[i][5] = fmaxf(__fadd_rn(acc[i][5], bi1.y), 0.0f);
        r_[i][6] = fmaxf(__fadd_rn(acc[i][6], bi1.z), 0.0f);
        r_[i][7] = fmaxf(__fadd_rn(acc[i][7], bi1.w), 0.0f);
    }
    const int row0 = by * 128 + tm * 8;
    if (!is_c1) {
#pragma unroll
        for (int j = 0; j < 8; j++) {
            const int col = cb + tn * 8 + j;
            float4 lo = make_float4(r_[0][j], r_[1][j], r_[2][j], r_[3][j]);
            float4 hi = make_float4(r_[4][j], r_[5][j], r_[6][j], r_[7][j]);
            float* cp = g_hT + (size_t)col * BATCH + row0;
            *(float4*)cp = lo;
            *(float4*)(cp + 4) = hi;
        }
    } else {
#pragma unroll
        for (int i = 0; i < 8; i++) {
            float* cp = g_c1 + (size_t)(row0 + i) * 128 + tn * 8;
            *(float4*)cp = make_float4(r_[i][0], r_[i][1], r_[i][2], r_[i][3]);
            *(float4*)(cp + 4) = make_float4(r_[i][4], r_[i][5], r_[i][6], r_[i][7]);
        }
    }
}

// ============================================================================
// scores GEMM (unchanged from R9): 256x128 CTA tile, 16x8 thread tile
// ============================================================================
#define AS_(buf,k,c) Asm[((buf)*16 + (k))*256 + (c)]
#define BS_(buf,k,c) Bsm[((buf)*16 + (k))*128 + (c)]

#define FRAG_LD3(av, bv, buf, k)                                                 \
    {   const float4* a4 = (const float4*)&AS_(buf, k, tm * 16);                 \
        float4 t0 = a4[0], t1 = a4[1], t2 = a4[2], t3 = a4[3];                   \
        float4 u0 = *(const float4*)&BS_(buf, k, tn * 4);                        \
        float4 u1 = *(const float4*)&BS_(buf, k, 64 + tn * 4);                   \
        av[0]=t0.x;  av[1]=t0.y;  av[2]=t0.z;  av[3]=t0.w;                       \
        av[4]=t1.x;  av[5]=t1.y;  av[6]=t1.z;  av[7]=t1.w;                       \
        av[8]=t2.x;  av[9]=t2.y;  av[10]=t2.z; av[11]=t2.w;                      \
        av[12]=t3.x; av[13]=t3.y; av[14]=t3.z; av[15]=t3.w;                      \
        bv[0]=u0.x; bv[1]=u0.y; bv[2]=u0.z; bv[3]=u0.w;                          \
        bv[4]=u1.x; bv[5]=u1.y; bv[6]=u1.z; bv[7]=u1.w;                          \
    }

#define FMA_BLOCK16(av, bv)                                                      \
    _Pragma("unroll")                                                            \
    for (int i = 0; i < 16; i++)                                                 \
        _Pragma("unroll")                                                        \
        for (int j = 0; j < 8; j++) acc[i][j] += av[i] * bv[j];

#define SC_SMEM (3 * 16 * 256 * 4 + 3 * 16 * 128 * 4)   // 73728 B

__global__ void __launch_bounds__(256, 1) sgemm_scores_ca(
    const float* __restrict__ AT, const float* __restrict__ B,
    const float* __restrict__ bias, const float* __restrict__ noise,
    float* __restrict__ C)
{
    extern __shared__ float smem_f[];
    float* Asm = smem_f;
    float* Bsm = smem_f + 3 * 16 * 256;
    const int bx = blockIdx.x, by = blockIdx.y;
    const int tid = threadIdx.x;
    const int tn = tid & 15, tm = tid >> 4;

    const int fa0 = tid, fa1 = tid + 256, fa2 = tid + 512, fa3 = tid + 768;
    const int ra0_ = fa0 >> 6, ca0_ = (fa0 & 63) * 4;
    const int ra1_ = fa1 >> 6, ca1_ = (fa1 & 63) * 4;
    const int ra2_ = fa2 >> 6, ca2_ = (fa2 & 63) * 4;
    const int ra3_ = fa3 >> 6, ca3_ = (fa3 & 63) * 4;
    const int fb0 = tid, fb1 = tid + 256;
    const int rb0_ = fb0 >> 5, cb0_ = (fb0 & 31) * 4;
    const int rb1_ = fb1 >> 5, cb1_ = (fb1 & 31) * 4;

    const float* gA0 = AT + (size_t)ra0_ * BATCH + by * 256 + ca0_;
    const float* gA1 = AT + (size_t)ra1_ * BATCH + by * 256 + ca1_;
    const float* gA2 = AT + (size_t)ra2_ * BATCH + by * 256 + ca2_;
    const float* gA3 = AT + (size_t)ra3_ * BATCH + by * 256 + ca3_;
    const float* gB0 = B  + (size_t)rb0_ * POOLN + bx * 128 + cb0_;
    const float* gB1 = B  + (size_t)rb1_ * POOLN + bx * 128 + cb1_;
    const size_t stepA = (size_t)16 * BATCH;
    const size_t stepB = (size_t)16 * POOLN;

#define CPA_TILE3(buf)                                                           \
    {   cpa16(&AS_(buf, ra0_, ca0_), gA0);                                       \
        cpa16(&AS_(buf, ra1_, ca1_), gA1);                                       \
        cpa16(&AS_(buf, ra2_, ca2_), gA2);                                       \
        cpa16(&AS_(buf, ra3_, ca3_), gA3);                                       \
        cpa16(&BS_(buf, rb0_, cb0_), gB0);                                       \
        cpa16(&BS_(buf, rb1_, cb1_), gB1);                                       \
        CP_COMMIT();                                                             \
        gA0 += stepA; gA1 += stepA; gA2 += stepA; gA3 += stepA;                  \
        gB0 += stepB; gB1 += stepB; }

    float acc[16][8];
#pragma unroll
    for (int i = 0; i < 16; i++)
#pragma unroll
        for (int j = 0; j < 8; j++) acc[i][j] = 0.0f;

    CPA_TILE3(0)
    CPA_TILE3(1)

    float af0[16], af1[16], bf0[8], bf1[8];
    const int ITERS = HIDN / 16;
    for (int it = 0; it < ITERS; it++) {
        const int cur = it % 3;
        CP_WAIT(1);
        __syncthreads();
        FRAG_LD3(af0, bf0, cur, 0)
#pragma unroll
        for (int k = 0; k < 15; k++) {
            if (k & 1) { FRAG_LD3(af0, bf0, cur, k + 1) FMA_BLOCK16(af1, bf1) }
            else       { FRAG_LD3(af1, bf1, cur, k + 1) FMA_BLOCK16(af0, bf0) }
        }
        if (it + 2 < ITERS) { CPA_TILE3((it + 2) % 3) }
        else                { CP_COMMIT(); }
        FMA_BLOCK16(af1, bf1)
    }

    const int colL = bx * 128 + tn * 4;
    const int colH = colL + 64;
    const float4 biL = *(const float4*)&bias[colL];
    const float4 biH = *(const float4*)&bias[colH];
#pragma unroll
    for (int i = 0; i < 16; i++) {
        const int row = by * 256 + tm * 16 + i;
        const float* np = noise + (size_t)row * POOLN;
        float4 nL = *(const float4*)(np + colL);
        float4 nH = *(const float4*)(np + colH);
        float4 oL, oH;
        oL.x = __fadd_rn(__fadd_rn(acc[i][0], biL.x), __fmul_rn(nL.x, 0.1f));
        oL.y = __fadd_rn(__fadd_rn(acc[i][1], biL.y), __fmul_rn(nL.y, 0.1f));
        oL.z = __fadd_rn(__fadd_rn(acc[i][2], biL.z), __fmul_rn(nL.z, 0.1f));
        oL.w = __fadd_rn(__fadd_rn(acc[i][3], biL.w), __fmul_rn(nL.w, 0.1f));
        oH.x = __fadd_rn(__fadd_rn(acc[i][4], biH.x), __fmul_rn(nH.x, 0.1f));
        oH.y = __fadd_rn(__fadd_rn(acc[i][5], biH.y), __fmul_rn(nH.y, 0.1f));
        oH.z = __fadd_rn(__fadd_rn(acc[i][6], biH.z), __fmul_rn(nH.z, 0.1f));
        oH.w = __fadd_rn(__fadd_rn(acc[i][7], biH.w), __fmul_rn(nH.w, 0.1f));
        float* cp = C + (size_t)row * POOLN;
        *(float4*)(cp + colL) = oL;
        *(float4*)(cp + colH) = oH;
    }
}

// ---------------- comp stage 2 / budget (unchanged) --------------------------
__global__ void comp_kernel(const float* __restrict__ W2c,
                            const float* __restrict__ b2c,
                            float* __restrict__ out_comp)
{
    int row  = blockIdx.x * 8 + (threadIdx.x >> 5);
    int lane = threadIdx.x & 31;
    float p = 0.0f;
#pragma unroll
    for (int t = lane; t < 128; t += 32) p += g_c1[row * 128 + t] * W2c[t];
#pragma unroll
    for (int o = 16; o > 0; o >>= 1) p += __shfl_down_sync(0xffffffffu, p, o);
    if (lane == 0) {
        float z = p + b2c[0];
        float c = 1.0f / (1.0f + expf(-z));
        g_comp[row]  = c;
        out_comp[row] = c;
    }
}

__global__ void budget_kernel(float* __restrict__ out_budget)
{
    __shared__ float ws[32];
    int tid = threadIdx.x;
    float s = g_comp[tid] + g_comp[tid + 1024];
#pragma unroll
    for (int o = 16; o > 0; o >>= 1) s += __shfl_down_sync(0xffffffffu, s, o);
    if ((tid & 31) == 0) ws[tid >> 5] = s;
    __syncthreads();
    if (tid < 32) {
        float v = ws[tid];
#pragma unroll
        for (int o = 16; o > 0; o >>= 1) v += __shfl_down_sync(0xffffffffu, v, o);
        if (tid == 0) {
            float mean  = v / 2048.0f;
            float scale = mean * mean;
            float t = 512.0f + 7680.0f * scale;
            int b = (int)floorf(t);
            if (b < MINP) b = MINP;
            if (b > MAXP) b = MAXP;
            g_budget = b;
            out_budget[0] = (float)b;
        }
    }
}

// ============================================================================
// top-k + softmax — selection now 8/12/12 with per-warp-private level-0 hist.
// ============================================================================
__device__ __forceinline__ unsigned f2key(float s) {
    unsigned b = __float_as_uint(s);
    return (b & 0x80000000u) ? ~b : (b | 0x80000000u);
}
__device__ __forceinline__ float key2f(unsigned k) {
    return __uint_as_float((k & 0x80000000u) ? (k ^ 0x80000000u) : ~k);
}
__device__ __forceinline__ u32 rec4(u32 b0, u32 b1, u32 b2, u32 b3, u32 d) {
    u32 m = (d & 1u) ? b0 : ~b0;
    m &= (d & 2u) ? b1 : ~b1;
    m &= (d & 4u) ? b2 : ~b2;
    m &= (d & 8u) ? b3 : ~b3;
    return m;
}

#define OFF_KEYA   0
#define OFF_KEYB   32768
#define OFF_IDXA   65536
#define OFF_IDXB   81920
#define OFF_SHIST  98304
#define OFF_RED    106496
#define TOPK_SMEM  (106496 + 384)

__global__ void __launch_bounds__(512, 2) topk_kernel(
    float* __restrict__ out_idx, float* __restrict__ out_w)
{
    extern __shared__ unsigned char smem_raw[];
    u32* keyA    = (u32*)(smem_raw + OFF_KEYA);
    u32* keyB    = (u32*)(smem_raw + OFF_KEYB);
    u16* idxA    = (u16*)(smem_raw + OFF_IDXA);
    u16* idxB    = (u16*)(smem_raw + OFF_IDXB);
    u32* shist   = (u32*)(smem_raw + OFF_SHIST);
    u32* selhist = (u32*)(smem_raw + OFF_KEYB);   // alias: 8192 u32 available
    u32* red     = (u32*)(smem_raw + OFF_RED);
    float* fred  = (float*)red;

    const int row = blockIdx.x;
    const int tid = threadIdx.x;
    const int w   = tid >> 5, lane = tid & 31;
    const unsigned ltm = (1u << lane) - 1u;
    const float* srow = g_scores + (size_t)row * POOLN;

    unsigned prefix = 0;
    u32 base_gt = 0;

    // ---- level 0: 8-bit digit, per-warp-private 256-bin histograms ---------
    {
#pragma unroll
        for (int i = 0; i < 8; i++) selhist[tid + i * 512] = 0;   // 16x256 bins
        __syncthreads();
        u32* myhist = selhist + w * 256;
#pragma unroll 1
        for (int itx = 0; itx < 16; itx++) {
            float4 v = *(const float4*)(srow + itx * 2048 + tid * 4);
            float sv[4] = {v.x, v.y, v.z, v.w};
#pragma unroll
            for (int c = 0; c < 4; c++) {
                u32 k = f2key(sv[c]);
                unsigned d = k >> 24;
                unsigned m = __match_any_sync(0xffffffffu, d);
                if ((m & ltm) == 0)
                    atomicAdd(&myhist[d], __popc(m));
            }
        }
        __syncthreads();
        // reduce 16 warps -> 256 col sums, then scan 256 (threads 0..255)
        u32 colsum = 0;
        if (tid < 256) {
#pragma unroll
            for (int ww = 0; ww < 16; ww++) colsum += selhist[ww * 256 + tid];
        }
        u32 inc = colsum;
#pragma unroll
        for (int o = 1; o < 32; o <<= 1) {
            u32 n = __shfl_up_sync(0xffffffffu, inc, o);
            if (lane >= o) inc += n;
        }
        if (lane == 31) red[w] = inc;   // warps 0..7 meaningful
        __syncthreads();
        if (tid < 32) {
            u32 v2 = (tid < 8) ? red[tid] : 0u;
#pragma unroll
            for (int o = 1; o < 32; o <<= 1) {
                u32 n = __shfl_up_sync(0xffffffffu, v2, o);
                if (tid >= o) v2 += n;
            }
            if (tid < 8) red[32 + tid] = v2;
        }
        __syncthreads();
        if (tid < 256) {
            u32 incl = inc + (w ? red[32 + w - 1] : 0u);   // inclusive prefix
            u32 T = red[32 + 7];
            u32 cg = T - incl;                              // digits > tid
            if (colsum && cg < MAXP && cg + colsum >= MAXP) {
                red[64] = (u32)tid;
                red[65] = cg;
            }
        }
        __syncthreads();
        prefix = red[64];
        base_gt += red[65];
        __syncthreads();
    }

    // ---- levels 1,2: 12-bit digits, shared 4096-bin hist (uniform spread) --
#pragma unroll 1
    for (int lvl = 1; lvl < 3; lvl++) {
        const int done = (lvl == 1) ? 8 : 20;
#pragma unroll
        for (int i = 0; i < 8; i++) selhist[tid + i * 512] = 0;
        __syncthreads();
#pragma unroll 1
        for (int itx = 0; itx < 16; itx++) {
            float4 v = *(const float4*)(srow + itx * 2048 + tid * 4);
            float sv[4] = {v.x, v.y, v.z, v.w};
#pragma unroll
            for (int c = 0; c < 4; c++) {
                u32 k = f2key(sv[c]);
                bool part = ((k >> (32 - done)) == prefix);
                unsigned d = part ? ((k << done) >> 20) : 0xFFFFFFFFu;
                unsigned m = __match_any_sync(0xffffffffu, d);
                if (part && (m & ltm) == 0)
                    atomicAdd(&selhist[d], __popc(m));
            }
        }
        __syncthreads();
        u32 h8[8], ex8[8];
#pragma unroll
        for (int i = 0; i < 8; i++) h8[i] = selhist[tid * 8 + i];
        u32 s = 0;
#pragma unroll
        for (int i = 0; i < 8; i++) s += h8[i];
        u32 inc = s;
#pragma unroll
        for (int o = 1; o < 32; o <<= 1) {
            u32 n = __shfl_up_sync(0xffffffffu, inc, o);
            if (lane >= o) inc += n;
        }
        if (lane == 31) red[w] = inc;
        __syncthreads();
        if (tid < 32) {
            u32 v2 = (tid < 16) ? red[tid] : 0u;
#pragma unroll
            for (int o = 1; o < 32; o <<= 1) {
                u32 n = __shfl_up_sync(0xffffffffu, v2, o);
                if (tid >= o) v2 += n;
            }
            if (tid < 16) red[32 + tid] = v2;
        }
        __syncthreads();
        u32 wb = (w == 0) ? 0u : red[32 + w - 1];
        u32 run = wb + inc - s;
#pragma unroll
        for (int i = 0; i < 8; i++) { ex8[i] = run; run += h8[i]; }
        u32 T = red[32 + 15];
#pragma unroll
        for (int i = 0; i < 8; i++) {
            u32 cg = T - ex8[i] - h8[i];
            if (h8[i] && base_gt + cg < MAXP && base_gt + cg + h8[i] >= MAXP) {
                red[64] = (u32)(tid * 8 + i);
                red[65] = cg;
            }
        }
        __syncthreads();
        prefix = (prefix << 12) | red[64];
        base_gt += red[65];
        __syncthreads();
    }
    const unsigned V = prefix;

    // ---- stable compaction (unchanged) --------------------------------------
    const int beg = tid * 64;
    int cgt = 0, ceq = 0;
#pragma unroll 4
    for (int q = 0; q < 16; q++) {
        float4 v = *(const float4*)(srow + beg + q * 4);
        float sv[4] = {v.x, v.y, v.z, v.w};
#pragma unroll
        for (int c = 0; c < 4; c++) {
            u32 k = f2key(sv[c]);
            cgt += (k > V); ceq += (k == V);
        }
    }
    int vg = cgt, ve = ceq;
#pragma unroll
    for (int o = 1; o < 32; o <<= 1) {
        int ng = __shfl_up_sync(0xffffffffu, vg, o);
        int ne = __shfl_up_sync(0xffffffffu, ve, o);
        if (lane >= o) { vg += ng; ve += ne; }
    }
    if (lane == 31) { red[w] = (u32)vg; red[16 + w] = (u32)ve; }
    __syncthreads();
    if (tid < 32) {
        int wg = (tid < 16) ? (int)red[tid] : 0;
        int we = (tid < 16) ? (int)red[16 + tid] : 0;
#pragma unroll
        for (int o = 1; o < 32; o <<= 1) {
            int ng = __shfl_up_sync(0xffffffffu, wg, o);
            int ne = __shfl_up_sync(0xffffffffu, we, o);
            if (tid >= o) { wg += ng; we += ne; }
        }
        if (tid < 16) { red[32 + tid] = (u32)wg; red[48 + tid] = (u32)we; }
    }
    __syncthreads();
    int bgt = vg - cgt + (w ? (int)red[32 + w - 1] : 0);
    int beq = ve - ceq + (w ? (int)red[48 + w - 1] : 0);
    const int count_gt = (int)red[32 + 15];
    const int need_eq  = MAXP - count_gt;

#pragma unroll 4
    for (int q = 0; q < 16; q++) {
        float4 v = *(const float4*)(srow + beg + q * 4);
        float sv[4] = {v.x, v.y, v.z, v.w};
#pragma unroll
        for (int c = 0; c < 4; c++) {
            u32 k = f2key(sv[c]);
            int j = beg + q * 4 + c;
            if (k > V) {
                keyA[bgt] = ~k; idxA[bgt] = (u16)j; bgt++;
            } else if (k == V) {
                int r = beq++;
                if (r < need_eq) {
                    keyA[count_gt + r] = ~V; idxA[count_gt + r] = (u16)j;
                }
            }
        }
    }
    __syncthreads();

    // ---- stable LSD radix sort (unchanged) ----------------------------------
    u32* ks = keyA; u32* kd = keyB;
    u16* is = idxA; u16* id_ = idxB;
#pragma unroll 1
    for (int p = 0; p < 8; p++) {
        const int shift = 4 * p;
#pragma unroll
        for (int i = 0; i < 4; i++) shist[tid + i * 512] = 0;
        __syncthreads();
        u32 kk0[8], kk1[8];
#pragma unroll
        for (int e = 0; e < 8; e++) {
            u32 k0 = ks[e * 1024 + tid * 2];
            u32 k1 = ks[e * 1024 + tid * 2 + 1];
            kk0[e] = k0; kk1[e] = k1;
            u32 d0 = (k0 >> shift) & 15u, d1 = (k1 >> shift) & 15u;
            u32 b0 = __ballot_sync(0xffffffffu, d0 & 1u);
            u32 b1 = __ballot_sync(0xffffffffu, (d0 >> 1) & 1u);
            u32 b2 = __ballot_sync(0xffffffffu, (d0 >> 2) & 1u);
            u32 b3 = __ballot_sync(0xffffffffu, (d0 >> 3) & 1u);
            u32 c0 = __ballot_sync(0xffffffffu, d1 & 1u);
            u32 c1 = __ballot_sync(0xffffffffu, (d1 >> 1) & 1u);
            u32 c2 = __ballot_sync(0xffffffffu, (d1 >> 2) & 1u);
            u32 c3 = __ballot_sync(0xffffffffu, (d1 >> 3) & 1u);
            if (lane < 16) {
                u32 cnt = (u32)__popc(rec4(b0, b1, b2, b3, lane))
                        + (u32)__popc(rec4(c0, c1, c2, c3, lane));
                shist[lane * 128 + e * 16 + w] = cnt;
            }
        }
        __syncthreads();
        {
            u32 h4[4];
#pragma unroll
            for (int i = 0; i < 4; i++) h4[i] = shist[tid * 4 + i];
            u32 s = h4[0] + h4[1] + h4[2] + h4[3];
            u32 inc = s;
#pragma unroll
            for (int o = 1; o < 32; o <<= 1) {
                u32 n = __shfl_up_sync(0xffffffffu, inc, o);
                if (lane >= o) inc += n;
            }
            if (lane == 31) red[w] = inc;
            __syncthreads();
            if (tid < 32) {
                u32 v2 = (tid < 16) ? red[tid] : 0u;
#pragma unroll
                for (int o = 1; o < 32; o <<= 1) {
                    u32 n = __shfl_up_sync(0xffffffffu, v2, o);
                    if (tid >= o) v2 += n;
                }
                if (tid < 16) red[32 + tid] = v2;
            }
            __syncthreads();
            u32 wb = (w == 0) ? 0u : red[32 + w - 1];
            u32 run = wb + inc - s;
#pragma unroll
            for (int i = 0; i < 4; i++) { shist[tid * 4 + i] = run; run += h4[i]; }
        }
        __syncthreads();
#pragma unroll
        for (int e = 0; e < 8; e++) {
            u32 k0 = kk0[e], k1 = kk1[e];
            u32 d0 = (k0 >> shift) & 15u, d1 = (k1 >> shift) & 15u;
            u32 b0 = __ballot_sync(0xffffffffu, d0 & 1u);
            u32 b1 = __ballot_sync(0xffffffffu, (d0 >> 1) & 1u);
            u32 b2 = __ballot_sync(0xffffffffu, (d0 >> 2) & 1u);
            u32 b3 = __ballot_sync(0xffffffffu, (d0 >> 3) & 1u);
            u32 c0 = __ballot_sync(0xffffffffu, d1 & 1u);
            u32 c1 = __ballot_sync(0xffffffffu, (d1 >> 1) & 1u);
            u32 c2 = __ballot_sync(0xffffffffu, (d1 >> 2) & 1u);
            u32 c3 = __ballot_sync(0xffffffffu, (d1 >> 3) & 1u);
            u32 r0 = (u32)__popc(rec4(b0,b1,b2,b3,d0) & ltm)
                   + (u32)__popc(rec4(c0,c1,c2,c3,d0) & ltm);
            u32 r1 = (u32)__popc(rec4(b0,b1,b2,b3,d1) & ltm)
                   + (u32)__popc(rec4(c0,c1,c2,c3,d1) & ltm)
                   + (d0 == d1 ? 1u : 0u);
            u32 p0 = shist[d0 * 128 + e * 16 + w] + r0;
            u32 p1 = shist[d1 * 128 + e * 16 + w] + r1;
            kd[p0] = k0; id_[p0] = is[e * 1024 + tid * 2];
            kd[p1] = k1; id_[p1] = is[e * 1024 + tid * 2 + 1];
        }
        __syncthreads();
        u32* tk = ks; ks = kd; kd = tk;
        u16* ti = is; is = id_; id_ = ti;
    }

    // ---- softmax over first `budget` entries (unchanged) --------------------
    const float s0 = key2f(~ks[0]);
    const int budget = g_budget;
    float part = 0.0f;
    float ev[16]; u16 iv[16];
#pragma unroll
    for (int i = 0; i < 16; i++) {
        int pp = tid + i * 512;
        u32 kk = ks[pp];
        iv[i] = is[pp];
        float e = (pp < budget) ? expf(key2f(~kk) - s0) : 0.0f;
        ev[i] = e;
        part += e;
    }
#pragma unroll
    for (int o = 16; o > 0; o >>= 1) part += __shfl_down_sync(0xffffffffu, part, o);
    __syncthreads();
    if (lane == 0) fred[66 + w] = part;
    __syncthreads();
    if (tid == 0) {
        float s = 0.0f;
        for (int ww = 0; ww < 16; ww++) s += fred[66 + ww];
        fred[82] = s;
    }
    __syncthreads();
    const float denom = fred[82];

#pragma unroll
    for (int i = 0; i < 16; i++) {
        int pp = tid + i * 512;
        out_idx[(size_t)row * MAXP + pp] = (float)iv[i];
        out_w  [(size_t)row * MAXP + pp] = ev[i] / denom;
    }
}

// ---------------- launch -----------------------------------------------------
extern "C" void kernel_launch(void* const* d_in, const int* in_sizes, int n_in,
                              void* d_out, int out_size)
{
    const float* x    = (const float*)d_in[0];
    const float* noise= (const float*)d_in[1];
    const float* W1c  = (const float*)d_in[2];
    const float* b1c  = (const float*)d_in[3];
    const float* W2c  = (const float*)d_in[4];
    const float* b2c  = (const float*)d_in[5];
    const float* Ws1  = (const float*)d_in[6];
    const float* bs1  = (const float*)d_in[7];
    const float* Ws2  = (const float*)d_in[8];
    const float* bs2  = (const float*)d_in[9];

    float* out        = (float*)d_out;
    float* out_idx    = out;
    float* out_budget = out + (size_t)BATCH * MAXP;
    float* out_w      = out_budget + 1;
    float* out_comp   = out_w + (size_t)BATCH * MAXP;

    float *hTp, *sp;
    cudaGetSymbolAddress((void**)&hTp, g_hT);
    cudaGetSymbolAddress((void**)&sp,  g_scores);

    sgemm_fused<<<dim3(9, 16), 256>>>(x, Ws1, bs1, W1c, b1c);
    comp_kernel<<<256, 256>>>(W2c, b2c, out_comp);
    budget_kernel<<<1, 1024>>>(out_budget);

    cudaFuncSetAttribute(sgemm_scores_ca, cudaFuncAttributeMaxDynamicSharedMemorySize, SC_SMEM);
    sgemm_scores_ca<<<dim3(256, 8), 256, SC_SMEM>>>(hTp, Ws2, bs2, noise, sp);

    cudaFuncSetAttribute(topk_kernel, cudaFuncAttributeMaxDynamicSharedMemorySize, TOPK_SMEM);
    topk_kernel<<<BATCH, 512, TOPK_SMEM>>>(out_idx, out_w);
}